// round 1
// baseline (speedup 1.0000x reference)
#include <cuda_runtime.h>
#include <math.h>

#define NB 4
#define NN 5000
#define NKI 4
#define NE 80000
#define ND 512
#define NL 6
#define NLM 3

// -------- scratch (static device globals; no allocation) --------
static __device__ float g_x[NB * NN * ND];        // 41 MB
static __device__ float g_y[NB * NN * ND];        // 41 MB
static __device__ float g_h[NB * NN * 2 * ND];    // 82 MB
static __device__ int   g_deg[NN];
static __device__ int   g_rowstart[NN + 1];
static __device__ int   g_cursor[NN];
static __device__ int   g_perm[NE];

// ---------------- CSR construction ----------------
__global__ void zero_deg_kernel() {
    int i = blockIdx.x * blockDim.x + threadIdx.x;
    if (i < NN) g_deg[i] = 0;
}

__global__ void count_dst_kernel(const int* __restrict__ dst) {
    int e = blockIdx.x * blockDim.x + threadIdx.x;
    if (e < NE) atomicAdd(&g_deg[dst[e]], 1);
}

__global__ void scan_deg_kernel() {
    __shared__ int sh[1024];
    __shared__ int carry;
    if (threadIdx.x == 0) carry = 0;
    __syncthreads();
    for (int base = 0; base < NN; base += 1024) {
        int i = base + threadIdx.x;
        int v = (i < NN) ? g_deg[i] : 0;
        sh[threadIdx.x] = v;
        __syncthreads();
        // Hillis-Steele inclusive scan
        for (int off = 1; off < 1024; off <<= 1) {
            int t = (threadIdx.x >= off) ? sh[threadIdx.x - off] : 0;
            __syncthreads();
            sh[threadIdx.x] += t;
            __syncthreads();
        }
        if (i < NN) {
            int excl = carry + sh[threadIdx.x] - v;
            g_rowstart[i] = excl;
            g_cursor[i]   = excl;
        }
        int tot = sh[1023];
        __syncthreads();
        if (threadIdx.x == 0) carry += tot;
        __syncthreads();
    }
    if (threadIdx.x == 0) g_rowstart[NN] = carry;
}

__global__ void scatter_edges_kernel(const int* __restrict__ dst) {
    int e = blockIdx.x * blockDim.x + threadIdx.x;
    if (e < NE) {
        int p = atomicAdd(&g_cursor[dst[e]], 1);
        g_perm[p] = e;
    }
}

// ---------------- embedding sum ----------------
__global__ void embed_kernel(const int* __restrict__ xidx, const float* __restrict__ emb) {
    int i = blockIdx.x * blockDim.x + threadIdx.x;  // over NB*NN*(ND/4)
    if (i >= NB * NN * (ND / 4)) return;
    int d4 = i & (ND / 4 - 1);
    int bn = i >> 7;  // ND/4 == 128
    int i0 = xidx[bn * NKI + 0];
    int i1 = xidx[bn * NKI + 1];
    int i2 = xidx[bn * NKI + 2];
    int i3 = xidx[bn * NKI + 3];
    const float4* E4 = (const float4*)emb;
    float4 a = E4[i0 * (ND / 4) + d4];
    float4 b = E4[i1 * (ND / 4) + d4];
    float4 c = E4[i2 * (ND / 4) + d4];
    float4 d = E4[i3 * (ND / 4) + d4];
    float4 s;
    s.x = a.x + b.x + c.x + d.x;
    s.y = a.y + b.y + c.y + d.y;
    s.z = a.z + b.z + c.z + d.z;
    s.w = a.w + b.w + c.w + d.w;
    ((float4*)g_x)[i] = s;
}

// ---------------- single-pass online segment-softmax aggregation ----------------
// For each (b, n): agg[d] = sum_e msg_e * exp(msg_e - max) / (sum_e exp(msg_e - max) + 1e-16)
// msg_e = relu(x[b, src_e, d] + ew_e) + 1e-7
// Output: y = agg + x
__global__ void msg_agg_kernel(const float* __restrict__ xin, float* __restrict__ yout,
                               const int* __restrict__ src, const float* __restrict__ ew) {
    int bn = blockIdx.x;                 // 0 .. NB*NN-1
    int b  = bn / NN;
    int n  = bn - b * NN;
    int t  = threadIdx.x;                // 0..127, each handles 4 features
    const float4* xb = (const float4*)(xin + (size_t)b * NN * ND);

    int s0 = g_rowstart[n];
    int s1 = g_rowstart[n + 1];

    float m[4], den[4], num[4];
#pragma unroll
    for (int c = 0; c < 4; c++) { m[c] = -3.4e38f; den[c] = 0.f; num[c] = 0.f; }

    for (int i = s0; i < s1; i++) {
        int   e  = g_perm[i];
        int   sn = src[e];
        float w  = ew[e];
        float4 v4 = xb[sn * (ND / 4) + t];
        float v[4] = {v4.x, v4.y, v4.z, v4.w};
#pragma unroll
        for (int c = 0; c < 4; c++) {
            float vv = fmaxf(v[c] + w, 0.f) + 1e-7f;
            if (vv > m[c]) {
                float sc = expf(m[c] - vv);   // first iter: exp(-huge) = 0
                den[c] = den[c] * sc + 1.f;
                num[c] = num[c] * sc + vv;
                m[c] = vv;
            } else {
                float sc = expf(vv - m[c]);
                den[c] += sc;
                num[c] += vv * sc;
            }
        }
    }

    float4 xi = xb[n * (ND / 4) + t];
    float ag[4];
#pragma unroll
    for (int c = 0; c < 4; c++)
        ag[c] = (s1 > s0) ? num[c] / (den[c] + 1e-16f) : 0.f;

    float4 o;
    o.x = ag[0] + xi.x;
    o.y = ag[1] + xi.y;
    o.z = ag[2] + xi.z;
    o.w = ag[3] + xi.w;
    ((float4*)(yout + (size_t)b * NN * ND))[n * (ND / 4) + t] = o;
}

// ---------------- SGEMM with fused epilogues ----------------
// C[M,N] = epilogue(A[M,K] @ B[K,N] + bias)
// MODE 0: ((acc+b1)*invsqrt(1+eps)*g1 + be1) -> relu      (conv GEMM1)
// MODE 1: relu(acc + b2)                                   (conv GEMM2 + outer relu)
// MODE 2: gelu_exact(acc + bm)                             (MLP)
#define GBM 128
#define GBN 128
#define GBK 8

template <int MODE>
__global__ void __launch_bounds__(256) sgemm_kernel(
    int M, int N, int K,
    const float* __restrict__ A, const float* __restrict__ B, float* __restrict__ C,
    const float* __restrict__ bias, const float* __restrict__ gsc, const float* __restrict__ bsh)
{
    __shared__ float As[GBK][GBM];
    __shared__ float Bs[GBK][GBN];

    int tid  = threadIdx.x;
    int bm0  = blockIdx.y * GBM;
    int bn0  = blockIdx.x * GBN;
    int arow = tid >> 1;
    int acol = (tid & 1) << 2;
    int brow = tid >> 5;
    int bcol = (tid & 31) << 2;
    int ty   = (tid >> 4) << 3;
    int tx   = (tid & 15) << 3;

    float acc[8][8];
#pragma unroll
    for (int i = 0; i < 8; i++)
#pragma unroll
        for (int j = 0; j < 8; j++) acc[i][j] = 0.f;

    int  gra  = bm0 + arow;
    bool aval = (gra < M);
    const float* Ap = A + (size_t)gra * K + acol;

    for (int k0 = 0; k0 < K; k0 += GBK) {
        float4 av = aval ? *(const float4*)(Ap + k0) : make_float4(0.f, 0.f, 0.f, 0.f);
        float4 bv = *(const float4*)(B + (size_t)(k0 + brow) * N + bn0 + bcol);
        As[acol + 0][arow] = av.x;
        As[acol + 1][arow] = av.y;
        As[acol + 2][arow] = av.z;
        As[acol + 3][arow] = av.w;
        *(float4*)&Bs[brow][bcol] = bv;
        __syncthreads();
#pragma unroll
        for (int kk = 0; kk < GBK; kk++) {
            float a[8], bb[8];
            *(float4*)&a[0]  = *(const float4*)&As[kk][ty];
            *(float4*)&a[4]  = *(const float4*)&As[kk][ty + 4];
            *(float4*)&bb[0] = *(const float4*)&Bs[kk][tx];
            *(float4*)&bb[4] = *(const float4*)&Bs[kk][tx + 4];
#pragma unroll
            for (int i = 0; i < 8; i++)
#pragma unroll
                for (int j = 0; j < 8; j++)
                    acc[i][j] = fmaf(a[i], bb[j], acc[i][j]);
        }
        __syncthreads();
    }

    const float invs = 0.9999950000374997f;  // 1/sqrt(1 + 1e-5)
#pragma unroll
    for (int i = 0; i < 8; i++) {
        int r = bm0 + ty + i;
        if (r >= M) return;
        float* Cr = C + (size_t)r * N + bn0 + tx;
#pragma unroll
        for (int j = 0; j < 8; j++) {
            int   cidx = bn0 + tx + j;
            float v = acc[i][j] + bias[cidx];
            if (MODE == 0) {
                v = v * invs * gsc[cidx] + bsh[cidx];
                v = fmaxf(v, 0.f);
            } else if (MODE == 1) {
                v = fmaxf(v, 0.f);
            } else {
                v = 0.5f * v * (1.f + erff(v * 0.7071067811865475f));
            }
            Cr[j] = v;
        }
    }
}

// ---------------- LayerNorm (two-pass, in-register) ----------------
__global__ void ln_kernel(const float* __restrict__ xin, float* __restrict__ yout,
                          const float* __restrict__ g, const float* __restrict__ bta) {
    int row = blockIdx.x;
    int t = threadIdx.x;  // 128
    __shared__ float red[4];
    float4 v = ((const float4*)(xin + (size_t)row * ND))[t];

    float s = v.x + v.y + v.z + v.w;
#pragma unroll
    for (int off = 16; off > 0; off >>= 1) s += __shfl_xor_sync(0xffffffff, s, off);
    if ((t & 31) == 0) red[t >> 5] = s;
    __syncthreads();
    float mu = (red[0] + red[1] + red[2] + red[3]) * (1.f / ND);
    __syncthreads();

    float dx = v.x - mu, dy = v.y - mu, dz = v.z - mu, dw = v.w - mu;
    float q = dx * dx + dy * dy + dz * dz + dw * dw;
#pragma unroll
    for (int off = 16; off > 0; off >>= 1) q += __shfl_xor_sync(0xffffffff, q, off);
    if ((t & 31) == 0) red[t >> 5] = q;
    __syncthreads();
    float var = (red[0] + red[1] + red[2] + red[3]) * (1.f / ND);
    float rs  = rsqrtf(var + 1e-5f);

    float4 gg = ((const float4*)g)[t];
    float4 bb = ((const float4*)bta)[t];
    float4 o;
    o.x = dx * rs * gg.x + bb.x;
    o.y = dy * rs * gg.y + bb.y;
    o.z = dz * rs * gg.z + bb.z;
    o.w = dw * rs * gg.w + bb.w;
    ((float4*)(yout + (size_t)row * ND))[t] = o;
}

// ---------------- output head ----------------
__global__ void zero_out_kernel(float* out) {
    if (threadIdx.x < NB) out[threadIdx.x] = 0.f;
}

__global__ void head_kernel(const float* __restrict__ h, const float* __restrict__ Wout,
                            const float* __restrict__ bout, float* __restrict__ out) {
    int row = blockIdx.x;  // 0 .. NB*NN-1
    int t = threadIdx.x;   // 128
    __shared__ float red[4];
    float4 v = ((const float4*)(h + (size_t)row * ND))[t];
    float4 w = ((const float4*)Wout)[t];
    float s = v.x * w.x + v.y * w.y + v.z * w.z + v.w * w.w;
#pragma unroll
    for (int off = 16; off > 0; off >>= 1) s += __shfl_xor_sync(0xffffffff, s, off);
    if ((t & 31) == 0) red[t >> 5] = s;
    __syncthreads();
    if (t == 0) {
        float tot = red[0] + red[1] + red[2] + red[3] + bout[0];
        atomicAdd(&out[row / NN], tot * (1.f / NN));
    }
}

// ---------------- launch ----------------
extern "C" void kernel_launch(void* const* d_in, const int* in_sizes, int n_in,
                              void* d_out, int out_size) {
    const int*   x_idx = (const int*)d_in[0];
    const int*   eidx  = (const int*)d_in[1];
    const float* ew    = (const float*)d_in[2];
    const float* emb   = (const float*)d_in[3];
    const float* W1    = (const float*)d_in[4];
    const float* b1    = (const float*)d_in[5];
    const float* g1    = (const float*)d_in[6];
    const float* be1   = (const float*)d_in[7];
    const float* W2    = (const float*)d_in[8];
    const float* b2    = (const float*)d_in[9];
    const float* ln_g  = (const float*)d_in[10];
    const float* ln_b  = (const float*)d_in[11];
    const float* Wm    = (const float*)d_in[12];
    const float* bm    = (const float*)d_in[13];
    const float* Wout  = (const float*)d_in[14];
    const float* bout  = (const float*)d_in[15];
    float* out = (float*)d_out;

    const int* src = eidx;        // edge_index[0]
    const int* dst = eidx + NE;   // edge_index[1]

    float *px, *py, *ph;
    cudaGetSymbolAddress((void**)&px, g_x);
    cudaGetSymbolAddress((void**)&py, g_y);
    cudaGetSymbolAddress((void**)&ph, g_h);

    // CSR build (deterministic work; intra-bucket order via atomics is
    // fp-insignificant at 1e-3 tolerance)
    zero_deg_kernel<<<(NN + 255) / 256, 256>>>();
    count_dst_kernel<<<(NE + 255) / 256, 256>>>(dst);
    scan_deg_kernel<<<1, 1024>>>();
    scatter_edges_kernel<<<(NE + 255) / 256, 256>>>(dst);

    // x = node_emb[x_idx].sum(axis=2)
    embed_kernel<<<(NB * NN * (ND / 4) + 255) / 256, 256>>>(x_idx, emb);

    const int M = NB * NN;
    dim3 gemm1_grid((2 * ND) / GBN, (M + GBM - 1) / GBM);
    dim3 gemm2_grid(ND / GBN, (M + GBM - 1) / GBM);

    for (int l = 0; l < NL; l++) {
        msg_agg_kernel<<<NB * NN, 128>>>(px, py, src, ew);
        sgemm_kernel<0><<<gemm1_grid, 256>>>(M, 2 * ND, ND,
                                             py, W1 + (size_t)l * ND * 2 * ND, ph,
                                             b1 + (size_t)l * 2 * ND,
                                             g1 + (size_t)l * 2 * ND,
                                             be1 + (size_t)l * 2 * ND);
        sgemm_kernel<1><<<gemm2_grid, 256>>>(M, ND, 2 * ND,
                                             ph, W2 + (size_t)l * 2 * ND * ND, px,
                                             b2 + (size_t)l * ND, nullptr, nullptr);
    }

    ln_kernel<<<NB * NN, 128>>>(px, py, ln_g, ln_b);

    dim3 gemmm_grid(ND / GBN, (M + GBM - 1) / GBM);
    sgemm_kernel<2><<<gemmm_grid, 256>>>(M, ND, ND, py, Wm, ph,
                                         bm, nullptr, nullptr);
    sgemm_kernel<2><<<gemmm_grid, 256>>>(M, ND, ND, ph, Wm + (size_t)ND * ND, py,
                                         bm + ND, nullptr, nullptr);
    sgemm_kernel<2><<<gemmm_grid, 256>>>(M, ND, ND, py, Wm + (size_t)2 * ND * ND, ph,
                                         bm + 2 * ND, nullptr, nullptr);

    zero_out_kernel<<<1, 32>>>(out);
    head_kernel<<<NB * NN, 128>>>(ph, Wout, bout, out);
}

// round 2
// speedup vs baseline: 2.3825x; 2.3825x over previous
#include <cuda_runtime.h>
#include <cuda_bf16.h>
#include <math.h>

#define NB 4
#define NN 5000
#define NKI 4
#define NE 80000
#define ND 512
#define NL 6
#define NLM 3

// -------- scratch (static device globals; no allocation) --------
static __device__ float g_x[NB * NN * ND];        // 41 MB
static __device__ float g_y[NB * NN * ND];        // 41 MB
static __device__ float g_h[NB * NN * 2 * ND];    // 82 MB
static __device__ int   g_deg[NN];
static __device__ int   g_rowstart[NN + 1];
static __device__ int   g_cursor[NN];
static __device__ int   g_perm[NE];

// ---------------- CSR construction ----------------
__global__ void zero_deg_kernel() {
    int i = blockIdx.x * blockDim.x + threadIdx.x;
    if (i < NN) g_deg[i] = 0;
}

__global__ void count_dst_kernel(const int* __restrict__ dst) {
    int e = blockIdx.x * blockDim.x + threadIdx.x;
    if (e < NE) atomicAdd(&g_deg[dst[e]], 1);
}

__global__ void scan_deg_kernel() {
    __shared__ int sh[1024];
    __shared__ int carry;
    if (threadIdx.x == 0) carry = 0;
    __syncthreads();
    for (int base = 0; base < NN; base += 1024) {
        int i = base + threadIdx.x;
        int v = (i < NN) ? g_deg[i] : 0;
        sh[threadIdx.x] = v;
        __syncthreads();
        for (int off = 1; off < 1024; off <<= 1) {
            int t = (threadIdx.x >= off) ? sh[threadIdx.x - off] : 0;
            __syncthreads();
            sh[threadIdx.x] += t;
            __syncthreads();
        }
        if (i < NN) {
            int excl = carry + sh[threadIdx.x] - v;
            g_rowstart[i] = excl;
            g_cursor[i]   = excl;
        }
        int tot = sh[1023];
        __syncthreads();
        if (threadIdx.x == 0) carry += tot;
        __syncthreads();
    }
    if (threadIdx.x == 0) g_rowstart[NN] = carry;
}

__global__ void scatter_edges_kernel(const int* __restrict__ dst) {
    int e = blockIdx.x * blockDim.x + threadIdx.x;
    if (e < NE) {
        int p = atomicAdd(&g_cursor[dst[e]], 1);
        g_perm[p] = e;
    }
}

// ---------------- embedding sum ----------------
__global__ void embed_kernel(const int* __restrict__ xidx, const float* __restrict__ emb) {
    int i = blockIdx.x * blockDim.x + threadIdx.x;
    if (i >= NB * NN * (ND / 4)) return;
    int d4 = i & (ND / 4 - 1);
    int bn = i >> 7;
    int i0 = xidx[bn * NKI + 0];
    int i1 = xidx[bn * NKI + 1];
    int i2 = xidx[bn * NKI + 2];
    int i3 = xidx[bn * NKI + 3];
    const float4* E4 = (const float4*)emb;
    float4 a = E4[i0 * (ND / 4) + d4];
    float4 b = E4[i1 * (ND / 4) + d4];
    float4 c = E4[i2 * (ND / 4) + d4];
    float4 d = E4[i3 * (ND / 4) + d4];
    float4 s;
    s.x = a.x + b.x + c.x + d.x;
    s.y = a.y + b.y + c.y + d.y;
    s.z = a.z + b.z + c.z + d.z;
    s.w = a.w + b.w + c.w + d.w;
    ((float4*)g_x)[i] = s;
}

// ---------------- single-pass online segment-softmax aggregation ----------------
__global__ void msg_agg_kernel(const float* __restrict__ xin, float* __restrict__ yout,
                               const int* __restrict__ src, const float* __restrict__ ew) {
    int bn = blockIdx.x;
    int b  = bn / NN;
    int n  = bn - b * NN;
    int t  = threadIdx.x;
    const float4* xb = (const float4*)(xin + (size_t)b * NN * ND);

    int s0 = g_rowstart[n];
    int s1 = g_rowstart[n + 1];

    float m[4], den[4], num[4];
#pragma unroll
    for (int c = 0; c < 4; c++) { m[c] = -3.4e38f; den[c] = 0.f; num[c] = 0.f; }

    for (int i = s0; i < s1; i++) {
        int   e  = g_perm[i];
        int   sn = src[e];
        float w  = ew[e];
        float4 v4 = xb[sn * (ND / 4) + t];
        float v[4] = {v4.x, v4.y, v4.z, v4.w};
#pragma unroll
        for (int c = 0; c < 4; c++) {
            float vv = fmaxf(v[c] + w, 0.f) + 1e-7f;
            if (vv > m[c]) {
                float sc = expf(m[c] - vv);
                den[c] = den[c] * sc + 1.f;
                num[c] = num[c] * sc + vv;
                m[c] = vv;
            } else {
                float sc = expf(vv - m[c]);
                den[c] += sc;
                num[c] += vv * sc;
            }
        }
    }

    float4 xi = xb[n * (ND / 4) + t];
    float ag[4];
#pragma unroll
    for (int c = 0; c < 4; c++)
        ag[c] = (s1 > s0) ? num[c] / (den[c] + 1e-16f) : 0.f;

    float4 o;
    o.x = ag[0] + xi.x;
    o.y = ag[1] + xi.y;
    o.z = ag[2] + xi.z;
    o.w = ag[3] + xi.w;
    ((float4*)(yout + (size_t)b * NN * ND))[n * (ND / 4) + t] = o;
}

// ---------------- tensor-core GEMM: split-bf16 emulated fp32 ----------------
// C = epilogue(A[M,K] @ B[K,N] + bias)
// A,B fp32 in gmem; split into bf16 hi/lo; D += Ah*Bh + Ah*Bl + Al*Bh (fp32 acc)
// MODE 0: BN-affine + relu ; MODE 1: relu ; MODE 2: exact GELU
#define BM 128
#define BN 128
#define BKF 32

__device__ __forceinline__ void ldsm_x4(unsigned& r0, unsigned& r1, unsigned& r2, unsigned& r3,
                                        const void* p) {
    unsigned a = (unsigned)__cvta_generic_to_shared(p);
    asm volatile("ldmatrix.sync.aligned.m8n8.x4.shared.b16 {%0,%1,%2,%3}, [%4];\n"
                 : "=r"(r0), "=r"(r1), "=r"(r2), "=r"(r3) : "r"(a));
}

__device__ __forceinline__ void ldsm_x2t(unsigned& r0, unsigned& r1, const void* p) {
    unsigned a = (unsigned)__cvta_generic_to_shared(p);
    asm volatile("ldmatrix.sync.aligned.m8n8.x2.trans.shared.b16 {%0,%1}, [%2];\n"
                 : "=r"(r0), "=r"(r1) : "r"(a));
}

__device__ __forceinline__ void mma_bf16(float* d, const unsigned* a, const unsigned* b) {
    asm volatile("mma.sync.aligned.m16n8k16.row.col.f32.bf16.bf16.f32 "
                 "{%0,%1,%2,%3}, {%4,%5,%6,%7}, {%8,%9}, {%0,%1,%2,%3};\n"
                 : "+f"(d[0]), "+f"(d[1]), "+f"(d[2]), "+f"(d[3])
                 : "r"(a[0]), "r"(a[1]), "r"(a[2]), "r"(a[3]), "r"(b[0]), "r"(b[1]));
}

__device__ __forceinline__ __nv_bfloat162 split_pair(float v, float& lo) {
    __nv_bfloat16 h = __float2bfloat16(v);
    lo = v - __bfloat162float(h);
    return __nv_bfloat162(h, h); // unused helper path, kept minimal below
}

template <int MODE>
__device__ __forceinline__ float gemm_ep(float v, float gv, float bv) {
    const float invs = 0.9999950000374997f;  // 1/sqrt(1+1e-5)
    if (MODE == 0) return fmaxf(v * invs * gv + bv, 0.f);
    if (MODE == 1) return fmaxf(v, 0.f);
    return 0.5f * v * (1.f + erff(v * 0.7071067811865475f));
}

template <int MODE>
__global__ void __launch_bounds__(256) bfgemm_kernel(
    int M, int N, int K,
    const float* __restrict__ A, const float* __restrict__ B, float* __restrict__ C,
    const float* __restrict__ bias, const float* __restrict__ gsc, const float* __restrict__ bsh)
{
    __shared__ __nv_bfloat16 Ah[BM][BKF + 8];
    __shared__ __nv_bfloat16 Al[BM][BKF + 8];
    __shared__ __nv_bfloat16 Bh[BKF][BN + 8];
    __shared__ __nv_bfloat16 Bl[BKF][BN + 8];

    const int tid  = threadIdx.x;
    const int lane = tid & 31;
    const int warp = tid >> 5;
    const int wm   = warp >> 2;   // 0..1 -> 64 rows each
    const int wn   = warp & 3;    // 0..3 -> 32 cols each
    const int bm0  = blockIdx.y * BM;
    const int bn0  = blockIdx.x * BN;

    const int arow = tid >> 3;        // 0..31
    const int acol = (tid & 7) * 4;   // 0,4,...,28

    float acc[4][4][4];
#pragma unroll
    for (int i = 0; i < 4; i++)
#pragma unroll
        for (int j = 0; j < 4; j++)
#pragma unroll
            for (int c = 0; c < 4; c++) acc[i][j][c] = 0.f;

    float4 areg[4], breg[4];

    // ---- prefetch first tile ----
#pragma unroll
    for (int i = 0; i < 4; i++) {
        int gr = bm0 + arow + 32 * i;
        areg[i] = (gr < M) ? *(const float4*)(A + (size_t)gr * K + acol)
                           : make_float4(0.f, 0.f, 0.f, 0.f);
        breg[i] = *(const float4*)(B + (size_t)arow * N + bn0 + acol + 32 * i);
    }

    for (int k0 = 0; k0 < K; k0 += BKF) {
        // ---- store current tile to smem (split hi/lo) ----
#pragma unroll
        for (int i = 0; i < 4; i++) {
            int r = arow + 32 * i;
            float vv[4] = {areg[i].x, areg[i].y, areg[i].z, areg[i].w};
            __nv_bfloat16 h[4], l[4];
#pragma unroll
            for (int c = 0; c < 4; c++) {
                h[c] = __float2bfloat16(vv[c]);
                l[c] = __float2bfloat16(vv[c] - __bfloat162float(h[c]));
            }
            *(__nv_bfloat162*)&Ah[r][acol]     = __halves2bfloat162(h[0], h[1]);
            *(__nv_bfloat162*)&Ah[r][acol + 2] = __halves2bfloat162(h[2], h[3]);
            *(__nv_bfloat162*)&Al[r][acol]     = __halves2bfloat162(l[0], l[1]);
            *(__nv_bfloat162*)&Al[r][acol + 2] = __halves2bfloat162(l[2], l[3]);

            float wv[4] = {breg[i].x, breg[i].y, breg[i].z, breg[i].w};
#pragma unroll
            for (int c = 0; c < 4; c++) {
                h[c] = __float2bfloat16(wv[c]);
                l[c] = __float2bfloat16(wv[c] - __bfloat162float(h[c]));
            }
            int bc = acol + 32 * i;
            *(__nv_bfloat162*)&Bh[arow][bc]     = __halves2bfloat162(h[0], h[1]);
            *(__nv_bfloat162*)&Bh[arow][bc + 2] = __halves2bfloat162(h[2], h[3]);
            *(__nv_bfloat162*)&Bl[arow][bc]     = __halves2bfloat162(l[0], l[1]);
            *(__nv_bfloat162*)&Bl[arow][bc + 2] = __halves2bfloat162(l[2], l[3]);
        }
        __syncthreads();

        // ---- prefetch next tile (overlaps with mma phase) ----
        if (k0 + BKF < K) {
            int kn = k0 + BKF;
#pragma unroll
            for (int i = 0; i < 4; i++) {
                int gr = bm0 + arow + 32 * i;
                areg[i] = (gr < M) ? *(const float4*)(A + (size_t)gr * K + kn + acol)
                                   : make_float4(0.f, 0.f, 0.f, 0.f);
                breg[i] = *(const float4*)(B + (size_t)(kn + arow) * N + bn0 + acol + 32 * i);
            }
        }

        // ---- compute: two k16 halves ----
#pragma unroll
        for (int ks = 0; ks < 2; ks++) {
            unsigned bhf[4][2], blf[4][2];
            int krow = ks * 16 + (lane & 7) + ((lane >> 3) & 1) * 8;
#pragma unroll
            for (int nt = 0; nt < 4; nt++) {
                int bc = wn * 32 + nt * 8;
                ldsm_x2t(bhf[nt][0], bhf[nt][1], &Bh[krow][bc]);
                ldsm_x2t(blf[nt][0], blf[nt][1], &Bl[krow][bc]);
            }
            int arr0 = wm * 64 + (lane & 7) + ((lane >> 3) & 1) * 8;
            int acq  = ks * 16 + ((lane >> 4) << 3);
#pragma unroll
            for (int mt = 0; mt < 4; mt++) {
                unsigned ahf[4], alf[4];
                ldsm_x4(ahf[0], ahf[1], ahf[2], ahf[3], &Ah[arr0 + mt * 16][acq]);
                ldsm_x4(alf[0], alf[1], alf[2], alf[3], &Al[arr0 + mt * 16][acq]);
#pragma unroll
                for (int nt = 0; nt < 4; nt++) {
                    mma_bf16(acc[mt][nt], ahf, bhf[nt]);
                    mma_bf16(acc[mt][nt], ahf, blf[nt]);
                    mma_bf16(acc[mt][nt], alf, bhf[nt]);
                }
            }
        }
        __syncthreads();
    }

    // ---- epilogue ----
#pragma unroll
    for (int mt = 0; mt < 4; mt++) {
        int r0 = bm0 + wm * 64 + mt * 16 + (lane >> 2);
        int r1 = r0 + 8;
#pragma unroll
        for (int nt = 0; nt < 4; nt++) {
            int c = bn0 + wn * 32 + nt * 8 + (lane & 3) * 2;
            float bi0 = bias[c], bi1 = bias[c + 1];
            float g0 = 0.f, g1 = 0.f, s0 = 0.f, s1 = 0.f;
            if (MODE == 0) { g0 = gsc[c]; g1 = gsc[c + 1]; s0 = bsh[c]; s1 = bsh[c + 1]; }
            if (r0 < M) {
                float2 o;
                o.x = gemm_ep<MODE>(acc[mt][nt][0] + bi0, g0, s0);
                o.y = gemm_ep<MODE>(acc[mt][nt][1] + bi1, g1, s1);
                *(float2*)(C + (size_t)r0 * N + c) = o;
            }
            if (r1 < M) {
                float2 o;
                o.x = gemm_ep<MODE>(acc[mt][nt][2] + bi0, g0, s0);
                o.y = gemm_ep<MODE>(acc[mt][nt][3] + bi1, g1, s1);
                *(float2*)(C + (size_t)r1 * N + c) = o;
            }
        }
    }
}

// ---------------- LayerNorm ----------------
__global__ void ln_kernel(const float* __restrict__ xin, float* __restrict__ yout,
                          const float* __restrict__ g, const float* __restrict__ bta) {
    int row = blockIdx.x;
    int t = threadIdx.x;
    __shared__ float red[4];
    float4 v = ((const float4*)(xin + (size_t)row * ND))[t];

    float s = v.x + v.y + v.z + v.w;
#pragma unroll
    for (int off = 16; off > 0; off >>= 1) s += __shfl_xor_sync(0xffffffff, s, off);
    if ((t & 31) == 0) red[t >> 5] = s;
    __syncthreads();
    float mu = (red[0] + red[1] + red[2] + red[3]) * (1.f / ND);
    __syncthreads();

    float dx = v.x - mu, dy = v.y - mu, dz = v.z - mu, dw = v.w - mu;
    float q = dx * dx + dy * dy + dz * dz + dw * dw;
#pragma unroll
    for (int off = 16; off > 0; off >>= 1) q += __shfl_xor_sync(0xffffffff, q, off);
    if ((t & 31) == 0) red[t >> 5] = q;
    __syncthreads();
    float var = (red[0] + red[1] + red[2] + red[3]) * (1.f / ND);
    float rs  = rsqrtf(var + 1e-5f);

    float4 gg = ((const float4*)g)[t];
    float4 bb = ((const float4*)bta)[t];
    float4 o;
    o.x = dx * rs * gg.x + bb.x;
    o.y = dy * rs * gg.y + bb.y;
    o.z = dz * rs * gg.z + bb.z;
    o.w = dw * rs * gg.w + bb.w;
    ((float4*)(yout + (size_t)row * ND))[t] = o;
}

// ---------------- output head ----------------
__global__ void zero_out_kernel(float* out) {
    if (threadIdx.x < NB) out[threadIdx.x] = 0.f;
}

__global__ void head_kernel(const float* __restrict__ h, const float* __restrict__ Wout,
                            const float* __restrict__ bout, float* __restrict__ out) {
    int row = blockIdx.x;
    int t = threadIdx.x;
    __shared__ float red[4];
    float4 v = ((const float4*)(h + (size_t)row * ND))[t];
    float4 w = ((const float4*)Wout)[t];
    float s = v.x * w.x + v.y * w.y + v.z * w.z + v.w * w.w;
#pragma unroll
    for (int off = 16; off > 0; off >>= 1) s += __shfl_xor_sync(0xffffffff, s, off);
    if ((t & 31) == 0) red[t >> 5] = s;
    __syncthreads();
    if (t == 0) {
        float tot = red[0] + red[1] + red[2] + red[3] + bout[0];
        atomicAdd(&out[row / NN], tot * (1.f / NN));
    }
}

// ---------------- launch ----------------
extern "C" void kernel_launch(void* const* d_in, const int* in_sizes, int n_in,
                              void* d_out, int out_size) {
    const int*   x_idx = (const int*)d_in[0];
    const int*   eidx  = (const int*)d_in[1];
    const float* ew    = (const float*)d_in[2];
    const float* emb   = (const float*)d_in[3];
    const float* W1    = (const float*)d_in[4];
    const float* b1    = (const float*)d_in[5];
    const float* g1    = (const float*)d_in[6];
    const float* be1   = (const float*)d_in[7];
    const float* W2    = (const float*)d_in[8];
    const float* b2    = (const float*)d_in[9];
    const float* ln_g  = (const float*)d_in[10];
    const float* ln_b  = (const float*)d_in[11];
    const float* Wm    = (const float*)d_in[12];
    const float* bm    = (const float*)d_in[13];
    const float* Wout  = (const float*)d_in[14];
    const float* bout  = (const float*)d_in[15];
    float* out = (float*)d_out;

    const int* src = eidx;
    const int* dst = eidx + NE;

    float *px, *py, *ph;
    cudaGetSymbolAddress((void**)&px, g_x);
    cudaGetSymbolAddress((void**)&py, g_y);
    cudaGetSymbolAddress((void**)&ph, g_h);

    zero_deg_kernel<<<(NN + 255) / 256, 256>>>();
    count_dst_kernel<<<(NE + 255) / 256, 256>>>(dst);
    scan_deg_kernel<<<1, 1024>>>();
    scatter_edges_kernel<<<(NE + 255) / 256, 256>>>(dst);

    embed_kernel<<<(NB * NN * (ND / 4) + 255) / 256, 256>>>(x_idx, emb);

    const int M = NB * NN;
    dim3 gemm1_grid((2 * ND) / BN, (M + BM - 1) / BM);
    dim3 gemm2_grid(ND / BN, (M + BM - 1) / BM);

    for (int l = 0; l < NL; l++) {
        msg_agg_kernel<<<NB * NN, 128>>>(px, py, src, ew);
        bfgemm_kernel<0><<<gemm1_grid, 256>>>(M, 2 * ND, ND,
                                              py, W1 + (size_t)l * ND * 2 * ND, ph,
                                              b1 + (size_t)l * 2 * ND,
                                              g1 + (size_t)l * 2 * ND,
                                              be1 + (size_t)l * 2 * ND);
        bfgemm_kernel<1><<<gemm2_grid, 256>>>(M, ND, 2 * ND,
                                              ph, W2 + (size_t)l * 2 * ND * ND, px,
                                              b2 + (size_t)l * ND, nullptr, nullptr);
    }

    ln_kernel<<<NB * NN, 128>>>(px, py, ln_g, ln_b);

    dim3 gemmm_grid(ND / BN, (M + BM - 1) / BM);
    bfgemm_kernel<2><<<gemmm_grid, 256>>>(M, ND, ND, py, Wm, ph,
                                          bm, nullptr, nullptr);
    bfgemm_kernel<2><<<gemmm_grid, 256>>>(M, ND, ND, ph, Wm + (size_t)ND * ND, py,
                                          bm + ND, nullptr, nullptr);
    bfgemm_kernel<2><<<gemmm_grid, 256>>>(M, ND, ND, py, Wm + (size_t)2 * ND * ND, ph,
                                          bm + 2 * ND, nullptr, nullptr);

    zero_out_kernel<<<1, 32>>>(out);
    head_kernel<<<NB * NN, 128>>>(ph, Wout, bout, out);
}

// round 4
// speedup vs baseline: 3.5960x; 1.5093x over previous
#include <cuda_runtime.h>
#include <cuda_bf16.h>
#include <math.h>
#include <stdint.h>

#define NB 4
#define NN 5000
#define NKI 4
#define NE 80000
#define ND 512
#define NL 6
#define NLM 3
#define MP 20096            // 157*128 padded rows

// ---------------- device scratch (zero-initialized; pads never read by non-GEMM) ----------------
static __device__ float         g_xf[MP * ND];                     // fp32 activations (msg path / head)
static __device__ __nv_bfloat16 g_y[MP * ND];                      // bf16 GEMM input (msg/LN/MLP out)
static __device__ __nv_bfloat16 g_h[MP * 2 * ND];                  // bf16 hidden
static __device__ __nv_bfloat16 g_w1hi[NL * 2 * ND * ND], g_w1lo[NL * 2 * ND * ND]; // [l][1024][512] K-major
static __device__ __nv_bfloat16 g_w2hi[NL * 2 * ND * ND], g_w2lo[NL * 2 * ND * ND]; // [l][512][1024]
static __device__ __nv_bfloat16 g_wmhi[NLM * ND * ND],    g_wmlo[NLM * ND * ND];    // [l][512][512]
static __device__ int g_deg[NN], g_rowstart[NN + 1], g_cursor[NN], g_perm[NE];

// ---------------- helpers ----------------
__device__ __forceinline__ uint32_t smem_u32(const void* p) {
    uint32_t a;
    asm("{ .reg .u64 t; cvta.to.shared.u64 t, %1; cvt.u32.u64 %0, t; }" : "=r"(a) : "l"(p));
    return a;
}
__device__ __forceinline__ void cp16(uint32_t sdst, const void* gsrc) {
    asm volatile("cp.async.cg.shared.global [%0], [%1], 16;" :: "r"(sdst), "l"(gsrc));
}
__device__ __forceinline__ void ldsm4(unsigned& r0, unsigned& r1, unsigned& r2, unsigned& r3, uint32_t a) {
    asm volatile("ldmatrix.sync.aligned.m8n8.x4.shared.b16 {%0,%1,%2,%3}, [%4];"
                 : "=r"(r0), "=r"(r1), "=r"(r2), "=r"(r3) : "r"(a));
}
__device__ __forceinline__ void mma_bf16(float* d, const unsigned* a, const unsigned* b) {
    asm volatile("mma.sync.aligned.m16n8k16.row.col.f32.bf16.bf16.f32 "
                 "{%0,%1,%2,%3}, {%4,%5,%6,%7}, {%8,%9}, {%0,%1,%2,%3};"
                 : "+f"(d[0]), "+f"(d[1]), "+f"(d[2]), "+f"(d[3])
                 : "r"(a[0]), "r"(a[1]), "r"(a[2]), "r"(a[3]), "r"(b[0]), "r"(b[1]));
}

// ---------------- CSR construction ----------------
__global__ void zero_deg_kernel() {
    int i = blockIdx.x * blockDim.x + threadIdx.x;
    if (i < NN) g_deg[i] = 0;
}
__global__ void count_dst_kernel(const int* __restrict__ dst) {
    int e = blockIdx.x * blockDim.x + threadIdx.x;
    if (e < NE) atomicAdd(&g_deg[dst[e]], 1);
}
__global__ void scan_deg_kernel() {
    __shared__ int sh[1024];
    __shared__ int carry;
    if (threadIdx.x == 0) carry = 0;
    __syncthreads();
    for (int base = 0; base < NN; base += 1024) {
        int i = base + threadIdx.x;
        int v = (i < NN) ? g_deg[i] : 0;
        sh[threadIdx.x] = v;
        __syncthreads();
        for (int off = 1; off < 1024; off <<= 1) {
            int t = (threadIdx.x >= off) ? sh[threadIdx.x - off] : 0;
            __syncthreads();
            sh[threadIdx.x] += t;
            __syncthreads();
        }
        if (i < NN) {
            int excl = carry + sh[threadIdx.x] - v;
            g_rowstart[i] = excl;
            g_cursor[i]   = excl;
        }
        int tot = sh[1023];
        __syncthreads();
        if (threadIdx.x == 0) carry += tot;
        __syncthreads();
    }
    if (threadIdx.x == 0) g_rowstart[NN] = carry;
}
__global__ void scatter_edges_kernel(const int* __restrict__ dst) {
    int e = blockIdx.x * blockDim.x + threadIdx.x;
    if (e < NE) {
        int p = atomicAdd(&g_cursor[dst[e]], 1);
        g_perm[p] = e;
    }
}

// ---------------- embedding sum ----------------
__global__ void embed_kernel(const int* __restrict__ xidx, const float* __restrict__ emb) {
    int i = blockIdx.x * blockDim.x + threadIdx.x;
    if (i >= NB * NN * (ND / 4)) return;
    int d4 = i & (ND / 4 - 1);
    int bn = i >> 7;
    int i0 = xidx[bn * NKI + 0], i1 = xidx[bn * NKI + 1];
    int i2 = xidx[bn * NKI + 2], i3 = xidx[bn * NKI + 3];
    const float4* E4 = (const float4*)emb;
    float4 a = E4[i0 * 128 + d4], b = E4[i1 * 128 + d4];
    float4 c = E4[i2 * 128 + d4], d = E4[i3 * 128 + d4];
    float4 s;
    s.x = a.x + b.x + c.x + d.x;
    s.y = a.y + b.y + c.y + d.y;
    s.z = a.z + b.z + c.z + d.z;
    s.w = a.w + b.w + c.w + d.w;
    ((float4*)g_xf)[i] = s;
}

// ---------------- weight transpose + bf16 split: T[n][k] = W[k][n] ----------------
__global__ void transpose_split_kernel(const float* __restrict__ W,
                                       __nv_bfloat16* __restrict__ Thi, __nv_bfloat16* __restrict__ Tlo,
                                       int Kd, int Nd) {
    __shared__ float t[32][33];
    int n0 = blockIdx.x * 32, k0 = blockIdx.y * 32;
    int tx = threadIdx.x, ty = threadIdx.y;
#pragma unroll
    for (int r = 0; r < 32; r += 8)
        t[ty + r][tx] = W[(size_t)(k0 + ty + r) * Nd + n0 + tx];
    __syncthreads();
#pragma unroll
    for (int r = 0; r < 32; r += 8) {
        float v = t[tx][ty + r];
        __nv_bfloat16 h = __float2bfloat16(v);
        size_t o = (size_t)(n0 + ty + r) * Kd + k0 + tx;
        Thi[o] = h;
        Tlo[o] = __float2bfloat16(v - __bfloat162float(h));
    }
}

// ---------------- single-pass online segment-softmax aggregation ----------------
__global__ void msg_agg_kernel(const float* __restrict__ xin, __nv_bfloat16* __restrict__ yout,
                               const int* __restrict__ src, const float* __restrict__ ew) {
    int bn = blockIdx.x;
    int b  = bn / NN;
    int n  = bn - b * NN;
    int t  = threadIdx.x;
    const float4* xb = (const float4*)(xin + (size_t)b * NN * ND);

    int s0 = g_rowstart[n], s1 = g_rowstart[n + 1];
    float m[4], den[4], num[4];
#pragma unroll
    for (int c = 0; c < 4; c++) { m[c] = -3.4e38f; den[c] = 0.f; num[c] = 0.f; }

    for (int i = s0; i < s1; i++) {
        int   e  = g_perm[i];
        int   sn = src[e];
        float w  = ew[e];
        float4 v4 = xb[sn * 128 + t];
        float v[4] = {v4.x, v4.y, v4.z, v4.w};
#pragma unroll
        for (int c = 0; c < 4; c++) {
            float vv = fmaxf(v[c] + w, 0.f) + 1e-7f;
            if (vv > m[c]) {
                float sc = expf(m[c] - vv);
                den[c] = den[c] * sc + 1.f;
                num[c] = num[c] * sc + vv;
                m[c] = vv;
            } else {
                float sc = expf(vv - m[c]);
                den[c] += sc;
                num[c] += vv * sc;
            }
        }
    }

    float4 xi = xb[n * 128 + t];
    float o0 = ((s1 > s0) ? num[0] / (den[0] + 1e-16f) : 0.f) + xi.x;
    float o1 = ((s1 > s0) ? num[1] / (den[1] + 1e-16f) : 0.f) + xi.y;
    float o2 = ((s1 > s0) ? num[2] / (den[2] + 1e-16f) : 0.f) + xi.z;
    float o3 = ((s1 > s0) ? num[3] / (den[3] + 1e-16f) : 0.f) + xi.w;

    size_t ob = (size_t)bn * ND + t * 4;
    *(__nv_bfloat162*)(yout + ob)     = __nv_bfloat162(__float2bfloat16(o0), __float2bfloat16(o1));
    *(__nv_bfloat162*)(yout + ob + 2) = __nv_bfloat162(__float2bfloat16(o2), __float2bfloat16(o3));
}

// ---------------- 2-term split GEMM on mma.sync (bf16) ----------------
// C[MP,N] = ep(A @ (Bhi + Blo)^T + bias); A bf16 [MP,K], B [N,K] K-major pre-split
// MODE 0: BN-affine+relu ; 1: relu ; 2: exact GELU.  WF32: 1 -> fp32 out, 0 -> bf16 out.
#define TPITCH 80          // 40 bf16 per row (32 data + 8 pad)
#define TBYTES 10240       // 128 rows * 80B
#define STG 30720          // 3 tensors
#define GSMEM (3 * STG)    // 3 stages

template <int MODE>
__device__ __forceinline__ float ep_apply(float v, float gv, float bv) {
    if (MODE == 0) return fmaxf(v * 0.9999950000374997f * gv + bv, 0.f);
    if (MODE == 1) return fmaxf(v, 0.f);
    return 0.5f * v * (1.f + erff(v * 0.7071067811865475f));
}

template <int MODE, int WF32>
__global__ void __launch_bounds__(256, 2) bfgemm2_kernel(
    int N, int K,
    const __nv_bfloat16* __restrict__ A,
    const __nv_bfloat16* __restrict__ Bhi, const __nv_bfloat16* __restrict__ Blo,
    float* __restrict__ Cf, __nv_bfloat16* __restrict__ Cb,
    const float* __restrict__ bias, const float* __restrict__ gsc, const float* __restrict__ bsh)
{
    extern __shared__ char smem[];
    const uint32_t sb = smem_u32(smem);
    const int tid = threadIdx.x, lane = tid & 31, warp = tid >> 5;
    const int wm = warp >> 2, wn = warp & 3;       // 2 x 4 warps, each 64x32
    const int bm0 = blockIdx.y * 128, bn0 = blockIdx.x * 128;
    const int KT = K >> 5;

    float acc[4][4][4];
#pragma unroll
    for (int i = 0; i < 4; i++)
#pragma unroll
        for (int j = 0; j < 4; j++)
#pragma unroll
            for (int c = 0; c < 4; c++) acc[i][j][c] = 0.f;

    auto load_stage = [&](int st, int kt) {
        uint32_t base = sb + st * STG;
        int k0 = kt * 32;
#pragma unroll
        for (int p = 0; p < 2; p++) {
            int cid = tid + 256 * p;       // 0..511
            int r = cid >> 2, c = cid & 3;
            uint32_t so = (uint32_t)(r * TPITCH + c * 16);
            size_t ga = (size_t)(bm0 + r) * K + k0 + c * 8;
            size_t gb = (size_t)(bn0 + r) * K + k0 + c * 8;
            cp16(base + so,              A   + ga);
            cp16(base + TBYTES + so,     Bhi + gb);
            cp16(base + 2 * TBYTES + so, Blo + gb);
        }
        asm volatile("cp.async.commit_group;");
    };

    load_stage(0, 0);
    load_stage(1, 1);

    const uint32_t arow = (uint32_t)(wm * 64 + (lane & 15));
    const uint32_t brow = (uint32_t)(wn * 32 + (lane & 7) + ((lane >> 4) << 3));
    const uint32_t akhi = (uint32_t)((lane >> 4) << 3);       // 0 or 8 (k-offset elems)
    const uint32_t bkhi = (uint32_t)(((lane >> 3) & 1) << 3); // 0 or 8

    for (int kt = 0; kt < KT; kt++) {
        asm volatile("cp.async.wait_group 1;");
        __syncthreads();
        uint32_t base = sb + (kt % 3) * STG;

#pragma unroll
        for (int ks = 0; ks < 2; ks++) {
            unsigned a[4][4], bh[4][2], bl[4][2];
            uint32_t acb = (uint32_t)((ks * 16 + akhi) * 2);
            uint32_t bcb = (uint32_t)((ks * 16 + bkhi) * 2);
#pragma unroll
            for (int mt = 0; mt < 4; mt++)
                ldsm4(a[mt][0], a[mt][1], a[mt][2], a[mt][3],
                      base + (arow + mt * 16) * TPITCH + acb);
            ldsm4(bh[0][0], bh[0][1], bh[1][0], bh[1][1], base + TBYTES + brow * TPITCH + bcb);
            ldsm4(bh[2][0], bh[2][1], bh[3][0], bh[3][1], base + TBYTES + (brow + 16) * TPITCH + bcb);
            ldsm4(bl[0][0], bl[0][1], bl[1][0], bl[1][1], base + 2 * TBYTES + brow * TPITCH + bcb);
            ldsm4(bl[2][0], bl[2][1], bl[3][0], bl[3][1], base + 2 * TBYTES + (brow + 16) * TPITCH + bcb);
#pragma unroll
            for (int mt = 0; mt < 4; mt++)
#pragma unroll
                for (int nt = 0; nt < 4; nt++) {
                    mma_bf16(acc[mt][nt], a[mt], bh[nt]);
                    mma_bf16(acc[mt][nt], a[mt], bl[nt]);
                }
        }

        if (kt + 2 < KT) load_stage((kt + 2) % 3, kt + 2);
        else asm volatile("cp.async.commit_group;");
        __syncthreads();
    }

    // ---- epilogue ----
#pragma unroll
    for (int nt = 0; nt < 4; nt++) {
        int c = bn0 + wn * 32 + nt * 8 + (lane & 3) * 2;
        float bi0 = bias[c], bi1 = bias[c + 1];
        float g0 = 0.f, g1 = 0.f, s0 = 0.f, s1 = 0.f;
        if (MODE == 0) { g0 = gsc[c]; g1 = gsc[c + 1]; s0 = bsh[c]; s1 = bsh[c + 1]; }
#pragma unroll
        for (int mt = 0; mt < 4; mt++) {
            size_t r0 = (size_t)(bm0 + wm * 64 + mt * 16 + (lane >> 2));
            size_t r1 = r0 + 8;
            float v00 = ep_apply<MODE>(acc[mt][nt][0] + bi0, g0, s0);
            float v01 = ep_apply<MODE>(acc[mt][nt][1] + bi1, g1, s1);
            float v10 = ep_apply<MODE>(acc[mt][nt][2] + bi0, g0, s0);
            float v11 = ep_apply<MODE>(acc[mt][nt][3] + bi1, g1, s1);
            if (WF32) {
                *(float2*)(Cf + r0 * N + c) = make_float2(v00, v01);
                *(float2*)(Cf + r1 * N + c) = make_float2(v10, v11);
            } else {
                *(__nv_bfloat162*)(Cb + r0 * N + c) =
                    __nv_bfloat162(__float2bfloat16(v00), __float2bfloat16(v01));
                *(__nv_bfloat162*)(Cb + r1 * N + c) =
                    __nv_bfloat162(__float2bfloat16(v10), __float2bfloat16(v11));
            }
        }
    }
}

// ---------------- LayerNorm -> bf16 ----------------
__global__ void ln_kernel(const float* __restrict__ xin, __nv_bfloat16* __restrict__ yout,
                          const float* __restrict__ g, const float* __restrict__ bta) {
    int row = blockIdx.x;
    int t = threadIdx.x;
    __shared__ float red[4];
    float4 v = ((const float4*)(xin + (size_t)row * ND))[t];

    float s = v.x + v.y + v.z + v.w;
#pragma unroll
    for (int off = 16; off > 0; off >>= 1) s += __shfl_xor_sync(0xffffffff, s, off);
    if ((t & 31) == 0) red[t >> 5] = s;
    __syncthreads();
    float mu = (red[0] + red[1] + red[2] + red[3]) * (1.f / ND);
    __syncthreads();

    float dx = v.x - mu, dy = v.y - mu, dz = v.z - mu, dw = v.w - mu;
    float q = dx * dx + dy * dy + dz * dz + dw * dw;
#pragma unroll
    for (int off = 16; off > 0; off >>= 1) q += __shfl_xor_sync(0xffffffff, q, off);
    if ((t & 31) == 0) red[t >> 5] = q;
    __syncthreads();
    float var = (red[0] + red[1] + red[2] + red[3]) * (1.f / ND);
    float rs  = rsqrtf(var + 1e-5f);

    float4 gg = ((const float4*)g)[t];
    float4 bb = ((const float4*)bta)[t];
    float o0 = dx * rs * gg.x + bb.x;
    float o1 = dy * rs * gg.y + bb.y;
    float o2 = dz * rs * gg.z + bb.z;
    float o3 = dw * rs * gg.w + bb.w;

    size_t ob = (size_t)row * ND + t * 4;
    *(__nv_bfloat162*)(yout + ob)     = __nv_bfloat162(__float2bfloat16(o0), __float2bfloat16(o1));
    *(__nv_bfloat162*)(yout + ob + 2) = __nv_bfloat162(__float2bfloat16(o2), __float2bfloat16(o3));
}

// ---------------- output head ----------------
__global__ void zero_out_kernel(float* out) {
    if (threadIdx.x < NB) out[threadIdx.x] = 0.f;
}
__global__ void head_kernel(const float* __restrict__ h, const float* __restrict__ Wout,
                            const float* __restrict__ bout, float* __restrict__ out) {
    int row = blockIdx.x;
    int t = threadIdx.x;
    __shared__ float red[4];
    float4 v = ((const float4*)(h + (size_t)row * ND))[t];
    float4 w = ((const float4*)Wout)[t];
    float s = v.x * w.x + v.y * w.y + v.z * w.z + v.w * w.w;
#pragma unroll
    for (int off = 16; off > 0; off >>= 1) s += __shfl_xor_sync(0xffffffff, s, off);
    if ((t & 31) == 0) red[t >> 5] = s;
    __syncthreads();
    if (t == 0) {
        float tot = red[0] + red[1] + red[2] + red[3] + bout[0];
        atomicAdd(&out[row / NN], tot * (1.f / NN));
    }
}

// ---------------- launch ----------------
extern "C" void kernel_launch(void* const* d_in, const int* in_sizes, int n_in,
                              void* d_out, int out_size) {
    const int*   x_idx = (const int*)d_in[0];
    const int*   eidx  = (const int*)d_in[1];
    const float* ew    = (const float*)d_in[2];
    const float* emb   = (const float*)d_in[3];
    const float* W1    = (const float*)d_in[4];
    const float* b1    = (const float*)d_in[5];
    const float* g1    = (const float*)d_in[6];
    const float* be1   = (const float*)d_in[7];
    const float* W2    = (const float*)d_in[8];
    const float* b2    = (const float*)d_in[9];
    const float* ln_g  = (const float*)d_in[10];
    const float* ln_b  = (const float*)d_in[11];
    const float* Wm    = (const float*)d_in[12];
    const float* bm    = (const float*)d_in[13];
    const float* Wout  = (const float*)d_in[14];
    const float* bout  = (const float*)d_in[15];
    float* out = (float*)d_out;

    const int* src = eidx;
    const int* dst = eidx + NE;

    float* pxf;
    __nv_bfloat16 *py, *ph, *w1hi, *w1lo, *w2hi, *w2lo, *wmhi, *wmlo;
    cudaGetSymbolAddress((void**)&pxf,  g_xf);
    cudaGetSymbolAddress((void**)&py,   g_y);
    cudaGetSymbolAddress((void**)&ph,   g_h);
    cudaGetSymbolAddress((void**)&w1hi, g_w1hi);
    cudaGetSymbolAddress((void**)&w1lo, g_w1lo);
    cudaGetSymbolAddress((void**)&w2hi, g_w2hi);
    cudaGetSymbolAddress((void**)&w2lo, g_w2lo);
    cudaGetSymbolAddress((void**)&wmhi, g_wmhi);
    cudaGetSymbolAddress((void**)&wmlo, g_wmlo);

    cudaFuncSetAttribute(bfgemm2_kernel<0, 0>, cudaFuncAttributeMaxDynamicSharedMemorySize, GSMEM);
    cudaFuncSetAttribute(bfgemm2_kernel<1, 1>, cudaFuncAttributeMaxDynamicSharedMemorySize, GSMEM);
    cudaFuncSetAttribute(bfgemm2_kernel<2, 0>, cudaFuncAttributeMaxDynamicSharedMemorySize, GSMEM);
    cudaFuncSetAttribute(bfgemm2_kernel<2, 1>, cudaFuncAttributeMaxDynamicSharedMemorySize, GSMEM);

    // CSR build
    zero_deg_kernel<<<(NN + 255) / 256, 256>>>();
    count_dst_kernel<<<(NE + 255) / 256, 256>>>(dst);
    scan_deg_kernel<<<1, 1024>>>();
    scatter_edges_kernel<<<(NE + 255) / 256, 256>>>(dst);

    // weight transpose + split
    dim3 tpb(32, 8);
    for (int l = 0; l < NL; l++) {
        transpose_split_kernel<<<dim3(2 * ND / 32, ND / 32), tpb>>>(
            W1 + (size_t)l * ND * 2 * ND, w1hi + (size_t)l * 2 * ND * ND, w1lo + (size_t)l * 2 * ND * ND, ND, 2 * ND);
        transpose_split_kernel<<<dim3(ND / 32, 2 * ND / 32), tpb>>>(
            W2 + (size_t)l * 2 * ND * ND, w2hi + (size_t)l * ND * 2 * ND, w2lo + (size_t)l * ND * 2 * ND, 2 * ND, ND);
    }
    for (int l = 0; l < NLM; l++)
        transpose_split_kernel<<<dim3(ND / 32, ND / 32), tpb>>>(
            Wm + (size_t)l * ND * ND, wmhi + (size_t)l * ND * ND, wmlo + (size_t)l * ND * ND, ND, ND);

    embed_kernel<<<(NB * NN * (ND / 4) + 255) / 256, 256>>>(x_idx, emb);

    const dim3 g1grid(8, MP / 128);   // N=1024
    const dim3 g2grid(4, MP / 128);   // N=512

    for (int l = 0; l < NL; l++) {
        msg_agg_kernel<<<NB * NN, 128>>>(pxf, py, src, ew);
        bfgemm2_kernel<0, 0><<<g1grid, 256, GSMEM>>>(
            2 * ND, ND, py,
            w1hi + (size_t)l * 2 * ND * ND, w1lo + (size_t)l * 2 * ND * ND,
            nullptr, ph,
            b1 + (size_t)l * 2 * ND, g1 + (size_t)l * 2 * ND, be1 + (size_t)l * 2 * ND);
        bfgemm2_kernel<1, 1><<<g2grid, 256, GSMEM>>>(
            ND, 2 * ND, ph,
            w2hi + (size_t)l * ND * 2 * ND, w2lo + (size_t)l * ND * 2 * ND,
            pxf, nullptr,
            b2 + (size_t)l * ND, nullptr, nullptr);
    }

    ln_kernel<<<NB * NN, 128>>>(pxf, py, ln_g, ln_b);

    bfgemm2_kernel<2, 0><<<g2grid, 256, GSMEM>>>(
        ND, ND, py, wmhi, wmlo, nullptr, ph, bm, nullptr, nullptr);
    bfgemm2_kernel<2, 0><<<g2grid, 256, GSMEM>>>(
        ND, ND, ph, wmhi + (size_t)ND * ND, wmlo + (size_t)ND * ND,
        nullptr, py, bm + ND, nullptr, nullptr);
    bfgemm2_kernel<2, 1><<<g2grid, 256, GSMEM>>>(
        ND, ND, py, wmhi + (size_t)2 * ND * ND, wmlo + (size_t)2 * ND * ND,
        pxf, nullptr, bm + 2 * ND, nullptr, nullptr);

    zero_out_kernel<<<1, 32>>>(out);
    head_kernel<<<NB * NN, 128>>>(pxf, Wout, bout, out);
}

// round 5
// speedup vs baseline: 3.6572x; 1.0170x over previous
#include <cuda_runtime.h>
#include <cuda_bf16.h>
#include <math.h>
#include <stdint.h>

#define NB 4
#define NN 5000
#define NKI 4
#define NE 80000
#define ND 512
#define NL 6
#define NLM 3
#define MP 20096            // 157*128 padded rows

// ---------------- device scratch (zero-initialized; pads never read by non-GEMM) ----------------
static __device__ __nv_bfloat16 g_xb[MP * ND];                     // bf16 activations x
static __device__ __nv_bfloat16 g_y[MP * ND];                      // bf16 GEMM input (msg/LN/MLP out)
static __device__ __nv_bfloat16 g_h[MP * 2 * ND];                  // bf16 hidden
static __device__ __nv_bfloat16 g_w1hi[NL * 2 * ND * ND], g_w1lo[NL * 2 * ND * ND]; // [l][1024][512] K-major
static __device__ __nv_bfloat16 g_w2hi[NL * 2 * ND * ND], g_w2lo[NL * 2 * ND * ND]; // [l][512][1024]
static __device__ __nv_bfloat16 g_wmhi[NLM * ND * ND],    g_wmlo[NLM * ND * ND];    // [l][512][512]
static __device__ int   g_deg[NN], g_rowstart[NN + 1], g_cursor[NN];
static __device__ int   g_esrc[NE];
static __device__ float g_eew[NE];

// ---------------- helpers ----------------
__device__ __forceinline__ uint32_t smem_u32(const void* p) {
    uint32_t a;
    asm("{ .reg .u64 t; cvta.to.shared.u64 t, %1; cvt.u32.u64 %0, t; }" : "=r"(a) : "l"(p));
    return a;
}
__device__ __forceinline__ void cp16(uint32_t sdst, const void* gsrc) {
    asm volatile("cp.async.cg.shared.global [%0], [%1], 16;" :: "r"(sdst), "l"(gsrc));
}
__device__ __forceinline__ void ldsm4(unsigned& r0, unsigned& r1, unsigned& r2, unsigned& r3, uint32_t a) {
    asm volatile("ldmatrix.sync.aligned.m8n8.x4.shared.b16 {%0,%1,%2,%3}, [%4];"
                 : "=r"(r0), "=r"(r1), "=r"(r2), "=r"(r3) : "r"(a));
}
__device__ __forceinline__ void mma_bf16(float* d, const unsigned* a, const unsigned* b) {
    asm volatile("mma.sync.aligned.m16n8k16.row.col.f32.bf16.bf16.f32 "
                 "{%0,%1,%2,%3}, {%4,%5,%6,%7}, {%8,%9}, {%0,%1,%2,%3};"
                 : "+f"(d[0]), "+f"(d[1]), "+f"(d[2]), "+f"(d[3])
                 : "r"(a[0]), "r"(a[1]), "r"(a[2]), "r"(a[3]), "r"(b[0]), "r"(b[1]));
}

// ---------------- embedding sum -> bf16 ----------------
__global__ void embed_kernel(const int* __restrict__ xidx, const float* __restrict__ emb) {
    int i = blockIdx.x * blockDim.x + threadIdx.x;
    if (i >= NB * NN * (ND / 4)) return;
    int d4 = i & (ND / 4 - 1);
    int bn = i >> 7;
    int i0 = xidx[bn * NKI + 0], i1 = xidx[bn * NKI + 1];
    int i2 = xidx[bn * NKI + 2], i3 = xidx[bn * NKI + 3];
    const float4* E4 = (const float4*)emb;
    float4 a = E4[i0 * 128 + d4], b = E4[i1 * 128 + d4];
    float4 c = E4[i2 * 128 + d4], d = E4[i3 * 128 + d4];
    float s0 = a.x + b.x + c.x + d.x;
    float s1 = a.y + b.y + c.y + d.y;
    float s2 = a.z + b.z + c.z + d.z;
    float s3 = a.w + b.w + c.w + d.w;
    size_t ob = (size_t)bn * ND + d4 * 4;
    *(__nv_bfloat162*)(g_xb + ob)     = __nv_bfloat162(__float2bfloat16(s0), __float2bfloat16(s1));
    *(__nv_bfloat162*)(g_xb + ob + 2) = __nv_bfloat162(__float2bfloat16(s2), __float2bfloat16(s3));
}

// ---------------- CSR construction ----------------
__global__ void zero_deg_kernel() {
    int i = blockIdx.x * blockDim.x + threadIdx.x;
    if (i < NN) g_deg[i] = 0;
}
__global__ void count_dst_kernel(const int* __restrict__ dst) {
    int e = blockIdx.x * blockDim.x + threadIdx.x;
    if (e < NE) atomicAdd(&g_deg[dst[e]], 1);
}
__global__ void scan_deg_kernel() {
    __shared__ int sh[1024];
    __shared__ int carry;
    if (threadIdx.x == 0) carry = 0;
    __syncthreads();
    for (int base = 0; base < NN; base += 1024) {
        int i = base + threadIdx.x;
        int v = (i < NN) ? g_deg[i] : 0;
        sh[threadIdx.x] = v;
        __syncthreads();
        for (int off = 1; off < 1024; off <<= 1) {
            int t = (threadIdx.x >= off) ? sh[threadIdx.x - off] : 0;
            __syncthreads();
            sh[threadIdx.x] += t;
            __syncthreads();
        }
        if (i < NN) {
            int excl = carry + sh[threadIdx.x] - v;
            g_rowstart[i] = excl;
            g_cursor[i]   = excl;
        }
        int tot = sh[1023];
        __syncthreads();
        if (threadIdx.x == 0) carry += tot;
        __syncthreads();
    }
    if (threadIdx.x == 0) g_rowstart[NN] = carry;
}
// scatter permuted copies of src/ew directly (removes perm indirection from msg loop)
__global__ void scatter_edges_kernel(const int* __restrict__ dst, const int* __restrict__ src,
                                     const float* __restrict__ ew) {
    int e = blockIdx.x * blockDim.x + threadIdx.x;
    if (e < NE) {
        int p = atomicAdd(&g_cursor[dst[e]], 1);
        g_esrc[p] = src[e];
        g_eew[p]  = ew[e];
    }
}

// ---------------- single-pass online segment-softmax aggregation (bf16 in/out) ----------------
__global__ void msg_agg_kernel(const __nv_bfloat16* __restrict__ xin,
                               __nv_bfloat16* __restrict__ yout) {
    int bn = blockIdx.x;
    int b  = bn / NN;
    int n  = bn - b * NN;
    int t  = threadIdx.x;
    const __nv_bfloat16* xbase = xin + (size_t)b * NN * ND;

    int s0 = g_rowstart[n], s1 = g_rowstart[n + 1];
    float m[4], den[4], num[4];
#pragma unroll
    for (int c = 0; c < 4; c++) { m[c] = -3.4e38f; den[c] = 0.f; num[c] = 0.f; }

    for (int i = s0; i < s1; i++) {
        int   sn = g_esrc[i];
        float w  = g_eew[i];
        uint2 u = *(const uint2*)(xbase + (size_t)sn * ND + t * 4);
        __nv_bfloat162 p0 = *(const __nv_bfloat162*)&u.x;
        __nv_bfloat162 p1 = *(const __nv_bfloat162*)&u.y;
        float v[4] = {__bfloat162float(p0.x), __bfloat162float(p0.y),
                      __bfloat162float(p1.x), __bfloat162float(p1.y)};
#pragma unroll
        for (int c = 0; c < 4; c++) {
            float vv = fmaxf(v[c] + w, 0.f) + 1e-7f;
            if (vv > m[c]) {
                float sc = expf(m[c] - vv);
                den[c] = den[c] * sc + 1.f;
                num[c] = num[c] * sc + vv;
                m[c] = vv;
            } else {
                float sc = expf(vv - m[c]);
                den[c] += sc;
                num[c] += vv * sc;
            }
        }
    }

    uint2 us = *(const uint2*)(xbase + (size_t)n * ND + t * 4);
    __nv_bfloat162 q0 = *(const __nv_bfloat162*)&us.x;
    __nv_bfloat162 q1 = *(const __nv_bfloat162*)&us.y;
    float xi[4] = {__bfloat162float(q0.x), __bfloat162float(q0.y),
                   __bfloat162float(q1.x), __bfloat162float(q1.y)};
    float o[4];
#pragma unroll
    for (int c = 0; c < 4; c++)
        o[c] = ((s1 > s0) ? num[c] / (den[c] + 1e-16f) : 0.f) + xi[c];

    size_t ob = (size_t)bn * ND + t * 4;
    *(__nv_bfloat162*)(yout + ob)     = __nv_bfloat162(__float2bfloat16(o[0]), __float2bfloat16(o[1]));
    *(__nv_bfloat162*)(yout + ob + 2) = __nv_bfloat162(__float2bfloat16(o[2]), __float2bfloat16(o[3]));
}

// ---------------- batched weight transpose + bf16 split: T[l][n][k] = W[l][k][n] ----------------
__global__ void transpose_split_kernel(const float* __restrict__ W,
                                       __nv_bfloat16* __restrict__ Thi, __nv_bfloat16* __restrict__ Tlo,
                                       int Kd, int Nd) {
    __shared__ float t[32][33];
    size_t lofs = (size_t)blockIdx.z * Kd * Nd;
    const float* Wl = W + lofs;
    int n0 = blockIdx.x * 32, k0 = blockIdx.y * 32;
    int tx = threadIdx.x, ty = threadIdx.y;
#pragma unroll
    for (int r = 0; r < 32; r += 8)
        t[ty + r][tx] = Wl[(size_t)(k0 + ty + r) * Nd + n0 + tx];
    __syncthreads();
#pragma unroll
    for (int r = 0; r < 32; r += 8) {
        float v = t[tx][ty + r];
        __nv_bfloat16 h = __float2bfloat16(v);
        size_t o = lofs + (size_t)(n0 + ty + r) * Kd + k0 + tx;
        Thi[o] = h;
        Tlo[o] = __float2bfloat16(v - __bfloat162float(h));
    }
}

// ---------------- 2-term split GEMM on mma.sync (bf16), bf16 output ----------------
// C[MP,N] = ep(A @ (Bhi + Blo)^T + bias)
// MODE 0: BN-affine+relu ; 1: relu ; 2: exact GELU.
#define TPITCH 80          // 40 bf16 per row (32 data + 8 pad)
#define TBYTES 10240       // 128 rows * 80B
#define STG 30720          // 3 tensors
#define GSMEM (3 * STG)    // 3 stages

template <int MODE>
__device__ __forceinline__ float ep_apply(float v, float gv, float bv) {
    if (MODE == 0) return fmaxf(v * 0.9999950000374997f * gv + bv, 0.f);
    if (MODE == 1) return fmaxf(v, 0.f);
    return 0.5f * v * (1.f + erff(v * 0.7071067811865475f));
}

template <int MODE>
__global__ void __launch_bounds__(256, 2) bfgemm2_kernel(
    int N, int K,
    const __nv_bfloat16* __restrict__ A,
    const __nv_bfloat16* __restrict__ Bhi, const __nv_bfloat16* __restrict__ Blo,
    __nv_bfloat16* __restrict__ Cb,
    const float* __restrict__ bias, const float* __restrict__ gsc, const float* __restrict__ bsh)
{
    extern __shared__ char smem[];
    const uint32_t sb = smem_u32(smem);
    const int tid = threadIdx.x, lane = tid & 31, warp = tid >> 5;
    const int wm = warp >> 2, wn = warp & 3;       // 2 x 4 warps, each 64x32
    const int bm0 = blockIdx.y * 128, bn0 = blockIdx.x * 128;
    const int KT = K >> 5;

    float acc[4][4][4];
#pragma unroll
    for (int i = 0; i < 4; i++)
#pragma unroll
        for (int j = 0; j < 4; j++)
#pragma unroll
            for (int c = 0; c < 4; c++) acc[i][j][c] = 0.f;

    auto load_stage = [&](int st, int kt) {
        uint32_t base = sb + st * STG;
        int k0 = kt * 32;
#pragma unroll
        for (int p = 0; p < 2; p++) {
            int cid = tid + 256 * p;       // 0..511
            int r = cid >> 2, c = cid & 3;
            uint32_t so = (uint32_t)(r * TPITCH + c * 16);
            size_t ga = (size_t)(bm0 + r) * K + k0 + c * 8;
            size_t gb = (size_t)(bn0 + r) * K + k0 + c * 8;
            cp16(base + so,              A   + ga);
            cp16(base + TBYTES + so,     Bhi + gb);
            cp16(base + 2 * TBYTES + so, Blo + gb);
        }
        asm volatile("cp.async.commit_group;");
    };

    load_stage(0, 0);
    load_stage(1, 1);

    const uint32_t arow = (uint32_t)(wm * 64 + (lane & 15));
    const uint32_t brow = (uint32_t)(wn * 32 + (lane & 7) + ((lane >> 4) << 3));
    const uint32_t akhi = (uint32_t)((lane >> 4) << 3);
    const uint32_t bkhi = (uint32_t)(((lane >> 3) & 1) << 3);

    for (int kt = 0; kt < KT; kt++) {
        asm volatile("cp.async.wait_group 1;");
        __syncthreads();
        uint32_t base = sb + (kt % 3) * STG;

#pragma unroll
        for (int ks = 0; ks < 2; ks++) {
            unsigned a[4][4], bh[4][2], bl[4][2];
            uint32_t acb = (uint32_t)((ks * 16 + akhi) * 2);
            uint32_t bcb = (uint32_t)((ks * 16 + bkhi) * 2);
#pragma unroll
            for (int mt = 0; mt < 4; mt++)
                ldsm4(a[mt][0], a[mt][1], a[mt][2], a[mt][3],
                      base + (arow + mt * 16) * TPITCH + acb);
            ldsm4(bh[0][0], bh[0][1], bh[1][0], bh[1][1], base + TBYTES + brow * TPITCH + bcb);
            ldsm4(bh[2][0], bh[2][1], bh[3][0], bh[3][1], base + TBYTES + (brow + 16) * TPITCH + bcb);
            ldsm4(bl[0][0], bl[0][1], bl[1][0], bl[1][1], base + 2 * TBYTES + brow * TPITCH + bcb);
            ldsm4(bl[2][0], bl[2][1], bl[3][0], bl[3][1], base + 2 * TBYTES + (brow + 16) * TPITCH + bcb);
#pragma unroll
            for (int mt = 0; mt < 4; mt++)
#pragma unroll
                for (int nt = 0; nt < 4; nt++) {
                    mma_bf16(acc[mt][nt], a[mt], bh[nt]);
                    mma_bf16(acc[mt][nt], a[mt], bl[nt]);
                }
        }

        if (kt + 2 < KT) load_stage((kt + 2) % 3, kt + 2);
        else asm volatile("cp.async.commit_group;");
        __syncthreads();
    }

    // ---- epilogue (bf16 out) ----
#pragma unroll
    for (int nt = 0; nt < 4; nt++) {
        int c = bn0 + wn * 32 + nt * 8 + (lane & 3) * 2;
        float bi0 = bias[c], bi1 = bias[c + 1];
        float g0 = 0.f, g1 = 0.f, s0 = 0.f, s1 = 0.f;
        if (MODE == 0) { g0 = gsc[c]; g1 = gsc[c + 1]; s0 = bsh[c]; s1 = bsh[c + 1]; }
#pragma unroll
        for (int mt = 0; mt < 4; mt++) {
            size_t r0 = (size_t)(bm0 + wm * 64 + mt * 16 + (lane >> 2));
            size_t r1 = r0 + 8;
            float v00 = ep_apply<MODE>(acc[mt][nt][0] + bi0, g0, s0);
            float v01 = ep_apply<MODE>(acc[mt][nt][1] + bi1, g1, s1);
            float v10 = ep_apply<MODE>(acc[mt][nt][2] + bi0, g0, s0);
            float v11 = ep_apply<MODE>(acc[mt][nt][3] + bi1, g1, s1);
            *(__nv_bfloat162*)(Cb + r0 * N + c) =
                __nv_bfloat162(__float2bfloat16(v00), __float2bfloat16(v01));
            *(__nv_bfloat162*)(Cb + r1 * N + c) =
                __nv_bfloat162(__float2bfloat16(v10), __float2bfloat16(v11));
        }
    }
}

// ---------------- LayerNorm (bf16 in/out) ----------------
__global__ void ln_kernel(const __nv_bfloat16* __restrict__ xin, __nv_bfloat16* __restrict__ yout,
                          const float* __restrict__ g, const float* __restrict__ bta) {
    int row = blockIdx.x;
    int t = threadIdx.x;
    __shared__ float red[4];
    uint2 u = *(const uint2*)(xin + (size_t)row * ND + t * 4);
    __nv_bfloat162 p0 = *(const __nv_bfloat162*)&u.x;
    __nv_bfloat162 p1 = *(const __nv_bfloat162*)&u.y;
    float v0 = __bfloat162float(p0.x), v1 = __bfloat162float(p0.y);
    float v2 = __bfloat162float(p1.x), v3 = __bfloat162float(p1.y);

    float s = v0 + v1 + v2 + v3;
#pragma unroll
    for (int off = 16; off > 0; off >>= 1) s += __shfl_xor_sync(0xffffffff, s, off);
    if ((t & 31) == 0) red[t >> 5] = s;
    __syncthreads();
    float mu = (red[0] + red[1] + red[2] + red[3]) * (1.f / ND);
    __syncthreads();

    float d0 = v0 - mu, d1 = v1 - mu, d2 = v2 - mu, d3 = v3 - mu;
    float q = d0 * d0 + d1 * d1 + d2 * d2 + d3 * d3;
#pragma unroll
    for (int off = 16; off > 0; off >>= 1) q += __shfl_xor_sync(0xffffffff, q, off);
    if ((t & 31) == 0) red[t >> 5] = q;
    __syncthreads();
    float var = (red[0] + red[1] + red[2] + red[3]) * (1.f / ND);
    float rs  = rsqrtf(var + 1e-5f);

    float4 gg = ((const float4*)g)[t];
    float4 bb = ((const float4*)bta)[t];
    float o0 = d0 * rs * gg.x + bb.x;
    float o1 = d1 * rs * gg.y + bb.y;
    float o2 = d2 * rs * gg.z + bb.z;
    float o3 = d3 * rs * gg.w + bb.w;

    size_t ob = (size_t)row * ND + t * 4;
    *(__nv_bfloat162*)(yout + ob)     = __nv_bfloat162(__float2bfloat16(o0), __float2bfloat16(o1));
    *(__nv_bfloat162*)(yout + ob + 2) = __nv_bfloat162(__float2bfloat16(o2), __float2bfloat16(o3));
}

// ---------------- output head (bf16 in) ----------------
__global__ void zero_out_kernel(float* out) {
    if (threadIdx.x < NB) out[threadIdx.x] = 0.f;
}
__global__ void head_kernel(const __nv_bfloat16* __restrict__ h, const float* __restrict__ Wout,
                            const float* __restrict__ bout, float* __restrict__ out) {
    int row = blockIdx.x;
    int t = threadIdx.x;
    __shared__ float red[4];
    uint2 u = *(const uint2*)(h + (size_t)row * ND + t * 4);
    __nv_bfloat162 p0 = *(const __nv_bfloat162*)&u.x;
    __nv_bfloat162 p1 = *(const __nv_bfloat162*)&u.y;
    float4 w = ((const float4*)Wout)[t];
    float s = __bfloat162float(p0.x) * w.x + __bfloat162float(p0.y) * w.y +
              __bfloat162float(p1.x) * w.z + __bfloat162float(p1.y) * w.w;
#pragma unroll
    for (int off = 16; off > 0; off >>= 1) s += __shfl_xor_sync(0xffffffff, s, off);
    if ((t & 31) == 0) red[t >> 5] = s;
    __syncthreads();
    if (t == 0) {
        float tot = red[0] + red[1] + red[2] + red[3] + bout[0];
        atomicAdd(&out[row / NN], tot * (1.f / NN));
    }
}

// ---------------- launch ----------------
extern "C" void kernel_launch(void* const* d_in, const int* in_sizes, int n_in,
                              void* d_out, int out_size) {
    const int*   x_idx = (const int*)d_in[0];
    const int*   eidx  = (const int*)d_in[1];
    const float* ew    = (const float*)d_in[2];
    const float* emb   = (const float*)d_in[3];
    const float* W1    = (const float*)d_in[4];
    const float* b1    = (const float*)d_in[5];
    const float* g1    = (const float*)d_in[6];
    const float* be1   = (const float*)d_in[7];
    const float* W2    = (const float*)d_in[8];
    const float* b2    = (const float*)d_in[9];
    const float* ln_g  = (const float*)d_in[10];
    const float* ln_b  = (const float*)d_in[11];
    const float* Wm    = (const float*)d_in[12];
    const float* bm    = (const float*)d_in[13];
    const float* Wout  = (const float*)d_in[14];
    const float* bout  = (const float*)d_in[15];
    float* out = (float*)d_out;

    const int* src = eidx;
    const int* dst = eidx + NE;

    __nv_bfloat16 *pxb, *py, *ph, *w1hi, *w1lo, *w2hi, *w2lo, *wmhi, *wmlo;
    cudaGetSymbolAddress((void**)&pxb,  g_xb);
    cudaGetSymbolAddress((void**)&py,   g_y);
    cudaGetSymbolAddress((void**)&ph,   g_h);
    cudaGetSymbolAddress((void**)&w1hi, g_w1hi);
    cudaGetSymbolAddress((void**)&w1lo, g_w1lo);
    cudaGetSymbolAddress((void**)&w2hi, g_w2hi);
    cudaGetSymbolAddress((void**)&w2lo, g_w2lo);
    cudaGetSymbolAddress((void**)&wmhi, g_wmhi);
    cudaGetSymbolAddress((void**)&wmlo, g_wmlo);

    cudaFuncSetAttribute(bfgemm2_kernel<0>, cudaFuncAttributeMaxDynamicSharedMemorySize, GSMEM);
    cudaFuncSetAttribute(bfgemm2_kernel<1>, cudaFuncAttributeMaxDynamicSharedMemorySize, GSMEM);
    cudaFuncSetAttribute(bfgemm2_kernel<2>, cudaFuncAttributeMaxDynamicSharedMemorySize, GSMEM);

    // launch order chosen so ncu (-s 5 -c 1) profiles msg_agg (launch #6)
    embed_kernel<<<(NB * NN * (ND / 4) + 255) / 256, 256>>>(x_idx, emb);      // 1
    zero_deg_kernel<<<(NN + 255) / 256, 256>>>();                             // 2
    count_dst_kernel<<<(NE + 255) / 256, 256>>>(dst);                         // 3
    scan_deg_kernel<<<1, 1024>>>();                                           // 4
    scatter_edges_kernel<<<(NE + 255) / 256, 256>>>(dst, src, ew);            // 5
    msg_agg_kernel<<<NB * NN, 128>>>(pxb, py);                                // 6 (layer 0)

    // batched weight transposes (3 launches)
    dim3 tpb(32, 8);
    transpose_split_kernel<<<dim3(2 * ND / 32, ND / 32, NL), tpb>>>(W1, w1hi, w1lo, ND, 2 * ND);
    transpose_split_kernel<<<dim3(ND / 32, 2 * ND / 32, NL), tpb>>>(W2, w2hi, w2lo, 2 * ND, ND);
    transpose_split_kernel<<<dim3(ND / 32, ND / 32, NLM), tpb>>>(Wm, wmhi, wmlo, ND, ND);

    const dim3 g1grid(8, MP / 128);   // N=1024
    const dim3 g2grid(4, MP / 128);   // N=512

    for (int l = 0; l < NL; l++) {
        if (l > 0) msg_agg_kernel<<<NB * NN, 128>>>(pxb, py);
        bfgemm2_kernel<0><<<g1grid, 256, GSMEM>>>(
            2 * ND, ND, py,
            w1hi + (size_t)l * 2 * ND * ND, w1lo + (size_t)l * 2 * ND * ND,
            ph,
            b1 + (size_t)l * 2 * ND, g1 + (size_t)l * 2 * ND, be1 + (size_t)l * 2 * ND);
        bfgemm2_kernel<1><<<g2grid, 256, GSMEM>>>(
            ND, 2 * ND, ph,
            w2hi + (size_t)l * ND * 2 * ND, w2lo + (size_t)l * ND * 2 * ND,
            pxb,
            b2 + (size_t)l * ND, nullptr, nullptr);
    }

    ln_kernel<<<NB * NN, 128>>>(pxb, py, ln_g, ln_b);

    bfgemm2_kernel<2><<<g2grid, 256, GSMEM>>>(
        ND, ND, py, wmhi, wmlo, ph, bm, nullptr, nullptr);
    bfgemm2_kernel<2><<<g2grid, 256, GSMEM>>>(
        ND, ND, ph, wmhi + (size_t)ND * ND, wmlo + (size_t)ND * ND,
        py, bm + ND, nullptr, nullptr);
    bfgemm2_kernel<2><<<g2grid, 256, GSMEM>>>(
        ND, ND, py, wmhi + (size_t)2 * ND * ND, wmlo + (size_t)2 * ND * ND,
        pxb, bm + 2 * ND, nullptr, nullptr);

    zero_out_kernel<<<1, 32>>>(out);
    head_kernel<<<NB * NN, 128>>>(pxb, Wout, bout, out);
}

// round 6
// speedup vs baseline: 3.6728x; 1.0043x over previous
#include <cuda_runtime.h>
#include <cuda_bf16.h>
#include <math.h>
#include <stdint.h>

#define NB 4
#define NN 5000
#define NKI 4
#define NE 80000
#define ND 512
#define NL 6
#define NLM 3
#define MP 20096            // 157*128 padded rows

// ---------------- device scratch (zero-initialized; pads never read by non-GEMM) ----------------
static __device__ __nv_bfloat16 g_xb[MP * ND];                     // bf16 activations x
static __device__ __nv_bfloat16 g_y[MP * ND];                      // bf16 GEMM input
static __device__ __nv_bfloat16 g_h[MP * 2 * ND];                  // bf16 hidden
static __device__ __nv_bfloat16 g_w1hi[NL * 2 * ND * ND], g_w1lo[NL * 2 * ND * ND];
static __device__ __nv_bfloat16 g_w2hi[NL * 2 * ND * ND], g_w2lo[NL * 2 * ND * ND];
static __device__ __nv_bfloat16 g_wmhi[NLM * ND * ND],    g_wmlo[NLM * ND * ND];
static __device__ int   g_deg[NN], g_rowstart[NN + 1], g_cursor[NN];
static __device__ int   g_esrc[NE];
static __device__ float g_eew[NE];

// ---------------- helpers ----------------
__device__ __forceinline__ uint32_t smem_u32(const void* p) {
    uint32_t a;
    asm("{ .reg .u64 t; cvta.to.shared.u64 t, %1; cvt.u32.u64 %0, t; }" : "=r"(a) : "l"(p));
    return a;
}
__device__ __forceinline__ void cp16(uint32_t sdst, const void* gsrc) {
    asm volatile("cp.async.cg.shared.global [%0], [%1], 16;" :: "r"(sdst), "l"(gsrc));
}
__device__ __forceinline__ void ldsm4(unsigned& r0, unsigned& r1, unsigned& r2, unsigned& r3, uint32_t a) {
    asm volatile("ldmatrix.sync.aligned.m8n8.x4.shared.b16 {%0,%1,%2,%3}, [%4];"
                 : "=r"(r0), "=r"(r1), "=r"(r2), "=r"(r3) : "r"(a));
}
__device__ __forceinline__ void mma_bf16(float* d, const unsigned* a, const unsigned* b) {
    asm volatile("mma.sync.aligned.m16n8k16.row.col.f32.bf16.bf16.f32 "
                 "{%0,%1,%2,%3}, {%4,%5,%6,%7}, {%8,%9}, {%0,%1,%2,%3};"
                 : "+f"(d[0]), "+f"(d[1]), "+f"(d[2]), "+f"(d[3])
                 : "r"(a[0]), "r"(a[1]), "r"(a[2]), "r"(a[3]), "r"(b[0]), "r"(b[1]));
}

// ---------------- embedding sum -> bf16 ----------------
__global__ void embed_kernel(const int* __restrict__ xidx, const float* __restrict__ emb) {
    int i = blockIdx.x * blockDim.x + threadIdx.x;
    if (i >= NB * NN * (ND / 4)) return;
    int d4 = i & (ND / 4 - 1);
    int bn = i >> 7;
    int i0 = xidx[bn * NKI + 0], i1 = xidx[bn * NKI + 1];
    int i2 = xidx[bn * NKI + 2], i3 = xidx[bn * NKI + 3];
    const float4* E4 = (const float4*)emb;
    float4 a = E4[i0 * 128 + d4], b = E4[i1 * 128 + d4];
    float4 c = E4[i2 * 128 + d4], d = E4[i3 * 128 + d4];
    float s0 = a.x + b.x + c.x + d.x;
    float s1 = a.y + b.y + c.y + d.y;
    float s2 = a.z + b.z + c.z + d.z;
    float s3 = a.w + b.w + c.w + d.w;
    size_t ob = (size_t)bn * ND + d4 * 4;
    *(__nv_bfloat162*)(g_xb + ob)     = __nv_bfloat162(__float2bfloat16(s0), __float2bfloat16(s1));
    *(__nv_bfloat162*)(g_xb + ob + 2) = __nv_bfloat162(__float2bfloat16(s2), __float2bfloat16(s3));
}

// ---------------- CSR construction ----------------
__global__ void zero_deg_kernel() {
    int i = blockIdx.x * blockDim.x + threadIdx.x;
    if (i < NN) g_deg[i] = 0;
}
__global__ void count_dst_kernel(const int* __restrict__ dst) {
    int e = blockIdx.x * blockDim.x + threadIdx.x;
    if (e < NE) atomicAdd(&g_deg[dst[e]], 1);
}
__global__ void scan_deg_kernel() {
    __shared__ int sh[1024];
    __shared__ int carry;
    if (threadIdx.x == 0) carry = 0;
    __syncthreads();
    for (int base = 0; base < NN; base += 1024) {
        int i = base + threadIdx.x;
        int v = (i < NN) ? g_deg[i] : 0;
        sh[threadIdx.x] = v;
        __syncthreads();
        for (int off = 1; off < 1024; off <<= 1) {
            int t = (threadIdx.x >= off) ? sh[threadIdx.x - off] : 0;
            __syncthreads();
            sh[threadIdx.x] += t;
            __syncthreads();
        }
        if (i < NN) {
            int excl = carry + sh[threadIdx.x] - v;
            g_rowstart[i] = excl;
            g_cursor[i]   = excl;
        }
        int tot = sh[1023];
        __syncthreads();
        if (threadIdx.x == 0) carry += tot;
        __syncthreads();
    }
    if (threadIdx.x == 0) g_rowstart[NN] = carry;
}
__global__ void scatter_edges_kernel(const int* __restrict__ dst, const int* __restrict__ src,
                                     const float* __restrict__ ew) {
    int e = blockIdx.x * blockDim.x + threadIdx.x;
    if (e < NE) {
        int p = atomicAdd(&g_cursor[dst[e]], 1);
        g_esrc[p] = src[e];
        g_eew[p]  = ew[e];
    }
}

// ---------------- single-pass online segment-softmax aggregation (bf16, prefetched) ----------------
__global__ void msg_agg_kernel(const __nv_bfloat16* __restrict__ xin,
                               __nv_bfloat16* __restrict__ yout) {
    int bn = blockIdx.x;
    int b  = bn / NN;
    int n  = bn - b * NN;
    int t  = threadIdx.x;
    const __nv_bfloat16* xbase = xin + (size_t)b * NN * ND;

    int s0 = g_rowstart[n], s1 = g_rowstart[n + 1];
    float m[4], den[4], num[4];
#pragma unroll
    for (int c = 0; c < 4; c++) { m[c] = -3.4e38f; den[c] = 0.f; num[c] = 0.f; }

    if (s1 > s0) {
        int   sn = g_esrc[s0];
        float w  = g_eew[s0];
        uint2 u  = *(const uint2*)(xbase + (size_t)sn * ND + t * 4);
        int i = s0;
        for (;;) {
            int ii = i + 1;
            bool more = (ii < s1);
            int sn2 = 0; float w2 = 0.f; uint2 u2 = make_uint2(0, 0);
            if (more) {
                sn2 = g_esrc[ii];
                w2  = g_eew[ii];
                u2  = *(const uint2*)(xbase + (size_t)sn2 * ND + t * 4);
            }
            __nv_bfloat162 p0 = *(const __nv_bfloat162*)&u.x;
            __nv_bfloat162 p1 = *(const __nv_bfloat162*)&u.y;
            float v[4] = {__bfloat162float(p0.x), __bfloat162float(p0.y),
                          __bfloat162float(p1.x), __bfloat162float(p1.y)};
#pragma unroll
            for (int c = 0; c < 4; c++) {
                float vv = fmaxf(v[c] + w, 0.f) + 1e-7f;
                if (vv > m[c]) {
                    float sc = expf(m[c] - vv);
                    den[c] = den[c] * sc + 1.f;
                    num[c] = num[c] * sc + vv;
                    m[c] = vv;
                } else {
                    float sc = expf(vv - m[c]);
                    den[c] += sc;
                    num[c] += vv * sc;
                }
            }
            if (!more) break;
            u = u2; w = w2; i = ii;
            (void)sn2;
        }
    }

    uint2 us = *(const uint2*)(xbase + (size_t)n * ND + t * 4);
    __nv_bfloat162 q0 = *(const __nv_bfloat162*)&us.x;
    __nv_bfloat162 q1 = *(const __nv_bfloat162*)&us.y;
    float xi[4] = {__bfloat162float(q0.x), __bfloat162float(q0.y),
                   __bfloat162float(q1.x), __bfloat162float(q1.y)};
    float o[4];
#pragma unroll
    for (int c = 0; c < 4; c++)
        o[c] = ((s1 > s0) ? num[c] / (den[c] + 1e-16f) : 0.f) + xi[c];

    size_t ob = (size_t)bn * ND + t * 4;
    *(__nv_bfloat162*)(yout + ob)     = __nv_bfloat162(__float2bfloat16(o[0]), __float2bfloat16(o[1]));
    *(__nv_bfloat162*)(yout + ob + 2) = __nv_bfloat162(__float2bfloat16(o[2]), __float2bfloat16(o[3]));
}

// ---------------- batched weight transpose + bf16 split ----------------
__global__ void transpose_split_kernel(const float* __restrict__ W,
                                       __nv_bfloat16* __restrict__ Thi, __nv_bfloat16* __restrict__ Tlo,
                                       int Kd, int Nd) {
    __shared__ float t[32][33];
    size_t lofs = (size_t)blockIdx.z * Kd * Nd;
    const float* Wl = W + lofs;
    int n0 = blockIdx.x * 32, k0 = blockIdx.y * 32;
    int tx = threadIdx.x, ty = threadIdx.y;
#pragma unroll
    for (int r = 0; r < 32; r += 8)
        t[ty + r][tx] = Wl[(size_t)(k0 + ty + r) * Nd + n0 + tx];
    __syncthreads();
#pragma unroll
    for (int r = 0; r < 32; r += 8) {
        float v = t[tx][ty + r];
        __nv_bfloat16 h = __float2bfloat16(v);
        size_t o = lofs + (size_t)(n0 + ty + r) * Kd + k0 + tx;
        Thi[o] = h;
        Tlo[o] = __float2bfloat16(v - __bfloat162float(h));
    }
}

// ---------------- 2-term split GEMM, 128x64 tiles, occ-3, single sync per k-iter ----------------
// MODE 0: BN-affine+relu ; 1: relu ; 2: exact GELU ; 3: GELU + fused output head
#define TPITCH 80
#define OFF_BH 10240       // A: 128*80
#define OFF_BL 15360       // Bhi: 64*80
#define STG 20480
#define GSMEM (3 * STG)

template <int MODE>
__device__ __forceinline__ float ep_apply(float v, float gv, float bv) {
    if (MODE == 0) return fmaxf(v * 0.9999950000374997f * gv + bv, 0.f);
    if (MODE == 1) return fmaxf(v, 0.f);
    return 0.5f * v * (1.f + erff(v * 0.7071067811865475f));
}

template <int MODE>
__global__ void __launch_bounds__(256, 3) bfgemm2_kernel(
    int N, int K,
    const __nv_bfloat16* __restrict__ A,
    const __nv_bfloat16* __restrict__ Bhi, const __nv_bfloat16* __restrict__ Blo,
    __nv_bfloat16* __restrict__ Cb,
    const float* __restrict__ bias, const float* __restrict__ gsc, const float* __restrict__ bsh,
    const float* __restrict__ wout, const float* __restrict__ boutp, float* __restrict__ outp)
{
    extern __shared__ char smem[];
    const uint32_t sb = smem_u32(smem);
    const int tid = threadIdx.x, lane = tid & 31, warp = tid >> 5;
    const int wm = warp >> 1, wn = warp & 1;       // 4 x 2 warps, each 32x32
    const int bm0 = blockIdx.y * 128, bn0 = blockIdx.x * 64;
    const int KT = K >> 5;

    float acc[2][4][4];
#pragma unroll
    for (int i = 0; i < 2; i++)
#pragma unroll
        for (int j = 0; j < 4; j++)
#pragma unroll
            for (int c = 0; c < 4; c++) acc[i][j][c] = 0.f;

    auto load_stage = [&](int st, int kt) {
        uint32_t base = sb + st * STG;
        int k0 = kt * 32;
#pragma unroll
        for (int p = 0; p < 2; p++) {
            int cid = tid + 256 * p;       // 0..511 -> A rows 0..127
            int r = cid >> 2, c = cid & 3;
            cp16(base + (uint32_t)(r * TPITCH + c * 16),
                 A + (size_t)(bm0 + r) * K + k0 + c * 8);
        }
        {
            int r = tid >> 2, c = tid & 3; // B rows 0..63
            uint32_t so = (uint32_t)(r * TPITCH + c * 16);
            size_t gb = (size_t)(bn0 + r) * K + k0 + c * 8;
            cp16(base + OFF_BH + so, Bhi + gb);
            cp16(base + OFF_BL + so, Blo + gb);
        }
        asm volatile("cp.async.commit_group;");
    };

    load_stage(0, 0);
    load_stage(1, 1);

    const uint32_t arow = (uint32_t)(wm * 32 + (lane & 15));
    const uint32_t brow = (uint32_t)(wn * 32 + (lane & 7) + ((lane >> 4) << 3));
    const uint32_t akhi = (uint32_t)((lane >> 4) << 3);
    const uint32_t bkhi = (uint32_t)(((lane >> 3) & 1) << 3);

    for (int kt = 0; kt < KT; kt++) {
        asm volatile("cp.async.wait_group 1;");
        __syncthreads();
        uint32_t base = sb + (kt % 3) * STG;

#pragma unroll
        for (int ks = 0; ks < 2; ks++) {
            unsigned a[2][4], bh[4][2], bl[4][2];
            uint32_t acb = (uint32_t)((ks * 16 + akhi) * 2);
            uint32_t bcb = (uint32_t)((ks * 16 + bkhi) * 2);
#pragma unroll
            for (int mt = 0; mt < 2; mt++)
                ldsm4(a[mt][0], a[mt][1], a[mt][2], a[mt][3],
                      base + (arow + mt * 16) * TPITCH + acb);
            ldsm4(bh[0][0], bh[0][1], bh[1][0], bh[1][1], base + OFF_BH + brow * TPITCH + bcb);
            ldsm4(bh[2][0], bh[2][1], bh[3][0], bh[3][1], base + OFF_BH + (brow + 16) * TPITCH + bcb);
            ldsm4(bl[0][0], bl[0][1], bl[1][0], bl[1][1], base + OFF_BL + brow * TPITCH + bcb);
            ldsm4(bl[2][0], bl[2][1], bl[3][0], bl[3][1], base + OFF_BL + (brow + 16) * TPITCH + bcb);
#pragma unroll
            for (int mt = 0; mt < 2; mt++)
#pragma unroll
                for (int nt = 0; nt < 4; nt++) {
                    mma_bf16(acc[mt][nt], a[mt], bh[nt]);
                    mma_bf16(acc[mt][nt], a[mt], bl[nt]);
                }
        }

        if (kt + 2 < KT) load_stage((kt + 2) % 3, kt + 2);
    }

    if (MODE != 3) {
        // ---- standard epilogue (bf16 out) ----
#pragma unroll
        for (int nt = 0; nt < 4; nt++) {
            int c = bn0 + wn * 32 + nt * 8 + (lane & 3) * 2;
            float bi0 = bias[c], bi1 = bias[c + 1];
            float g0 = 0.f, g1 = 0.f, s0 = 0.f, s1 = 0.f;
            if (MODE == 0) { g0 = gsc[c]; g1 = gsc[c + 1]; s0 = bsh[c]; s1 = bsh[c + 1]; }
#pragma unroll
            for (int mt = 0; mt < 2; mt++) {
                size_t r0 = (size_t)(bm0 + wm * 32 + mt * 16 + (lane >> 2));
                size_t r1 = r0 + 8;
                float v00 = ep_apply<MODE>(acc[mt][nt][0] + bi0, g0, s0);
                float v01 = ep_apply<MODE>(acc[mt][nt][1] + bi1, g1, s1);
                float v10 = ep_apply<MODE>(acc[mt][nt][2] + bi0, g0, s0);
                float v11 = ep_apply<MODE>(acc[mt][nt][3] + bi1, g1, s1);
                *(__nv_bfloat162*)(Cb + r0 * N + c) =
                    __nv_bfloat162(__float2bfloat16(v00), __float2bfloat16(v01));
                *(__nv_bfloat162*)(Cb + r1 * N + c) =
                    __nv_bfloat162(__float2bfloat16(v10), __float2bfloat16(v11));
            }
        }
    } else {
        // ---- fused output head: gelu -> dot(Wout) -> per-batch atomic ----
        __syncthreads();                       // smem stages no longer read; reuse as rowacc
        float* rowacc   = (float*)smem;        // 128 floats
        float* batchacc = (float*)(smem + 512);
        if (tid < 128) rowacc[tid] = 0.f;
        if (tid >= 128 && tid < 132) batchacc[tid - 128] = 0.f;
        __syncthreads();
#pragma unroll
        for (int mt = 0; mt < 2; mt++) {
            float hs0 = 0.f, hs1 = 0.f;
#pragma unroll
            for (int nt = 0; nt < 4; nt++) {
                int c = bn0 + wn * 32 + nt * 8 + (lane & 3) * 2;
                float bi0 = bias[c], bi1 = bias[c + 1];
                float v00 = ep_apply<2>(acc[mt][nt][0] + bi0, 0.f, 0.f);
                float v01 = ep_apply<2>(acc[mt][nt][1] + bi1, 0.f, 0.f);
                float v10 = ep_apply<2>(acc[mt][nt][2] + bi0, 0.f, 0.f);
                float v11 = ep_apply<2>(acc[mt][nt][3] + bi1, 0.f, 0.f);
                float w0 = wout[c], w1 = wout[c + 1];
                hs0 += v00 * w0 + v01 * w1;
                hs1 += v10 * w0 + v11 * w1;
            }
            int lr = wm * 32 + mt * 16 + (lane >> 2);
            atomicAdd(&rowacc[lr], hs0);
            atomicAdd(&rowacc[lr + 8], hs1);
        }
        __syncthreads();
        if (tid < 128) {
            int gr = bm0 + tid;
            if (gr < NB * NN) {
                float contrib = rowacc[tid];
                if (blockIdx.x == 0) contrib += boutp[0];
                atomicAdd(&batchacc[gr / NN], contrib);
            }
        }
        __syncthreads();
        if (tid < 4) atomicAdd(&outp[tid], batchacc[tid] * (1.f / NN));
    }
}

// ---------------- LayerNorm (bf16 in/out) ----------------
__global__ void ln_kernel(const __nv_bfloat16* __restrict__ xin, __nv_bfloat16* __restrict__ yout,
                          const float* __restrict__ g, const float* __restrict__ bta) {
    int row = blockIdx.x;
    int t = threadIdx.x;
    __shared__ float red[4];
    uint2 u = *(const uint2*)(xin + (size_t)row * ND + t * 4);
    __nv_bfloat162 p0 = *(const __nv_bfloat162*)&u.x;
    __nv_bfloat162 p1 = *(const __nv_bfloat162*)&u.y;
    float v0 = __bfloat162float(p0.x), v1 = __bfloat162float(p0.y);
    float v2 = __bfloat162float(p1.x), v3 = __bfloat162float(p1.y);

    float s = v0 + v1 + v2 + v3;
#pragma unroll
    for (int off = 16; off > 0; off >>= 1) s += __shfl_xor_sync(0xffffffff, s, off);
    if ((t & 31) == 0) red[t >> 5] = s;
    __syncthreads();
    float mu = (red[0] + red[1] + red[2] + red[3]) * (1.f / ND);
    __syncthreads();

    float d0 = v0 - mu, d1 = v1 - mu, d2 = v2 - mu, d3 = v3 - mu;
    float q = d0 * d0 + d1 * d1 + d2 * d2 + d3 * d3;
#pragma unroll
    for (int off = 16; off > 0; off >>= 1) q += __shfl_xor_sync(0xffffffff, q, off);
    if ((t & 31) == 0) red[t >> 5] = q;
    __syncthreads();
    float var = (red[0] + red[1] + red[2] + red[3]) * (1.f / ND);
    float rs  = rsqrtf(var + 1e-5f);

    float4 gg = ((const float4*)g)[t];
    float4 bb = ((const float4*)bta)[t];
    float o0 = d0 * rs * gg.x + bb.x;
    float o1 = d1 * rs * gg.y + bb.y;
    float o2 = d2 * rs * gg.z + bb.z;
    float o3 = d3 * rs * gg.w + bb.w;

    size_t ob = (size_t)row * ND + t * 4;
    *(__nv_bfloat162*)(yout + ob)     = __nv_bfloat162(__float2bfloat16(o0), __float2bfloat16(o1));
    *(__nv_bfloat162*)(yout + ob + 2) = __nv_bfloat162(__float2bfloat16(o2), __float2bfloat16(o3));
}

__global__ void zero_out_kernel(float* out) {
    if (threadIdx.x < NB) out[threadIdx.x] = 0.f;
}

// ---------------- launch ----------------
extern "C" void kernel_launch(void* const* d_in, const int* in_sizes, int n_in,
                              void* d_out, int out_size) {
    const int*   x_idx = (const int*)d_in[0];
    const int*   eidx  = (const int*)d_in[1];
    const float* ew    = (const float*)d_in[2];
    const float* emb   = (const float*)d_in[3];
    const float* W1    = (const float*)d_in[4];
    const float* b1    = (const float*)d_in[5];
    const float* g1    = (const float*)d_in[6];
    const float* be1   = (const float*)d_in[7];
    const float* W2    = (const float*)d_in[8];
    const float* b2    = (const float*)d_in[9];
    const float* ln_g  = (const float*)d_in[10];
    const float* ln_b  = (const float*)d_in[11];
    const float* Wm    = (const float*)d_in[12];
    const float* bm    = (const float*)d_in[13];
    const float* Wout  = (const float*)d_in[14];
    const float* bout  = (const float*)d_in[15];
    float* out = (float*)d_out;

    const int* src = eidx;
    const int* dst = eidx + NE;

    __nv_bfloat16 *pxb, *py, *ph, *w1hi, *w1lo, *w2hi, *w2lo, *wmhi, *wmlo;
    cudaGetSymbolAddress((void**)&pxb,  g_xb);
    cudaGetSymbolAddress((void**)&py,   g_y);
    cudaGetSymbolAddress((void**)&ph,   g_h);
    cudaGetSymbolAddress((void**)&w1hi, g_w1hi);
    cudaGetSymbolAddress((void**)&w1lo, g_w1lo);
    cudaGetSymbolAddress((void**)&w2hi, g_w2hi);
    cudaGetSymbolAddress((void**)&w2lo, g_w2lo);
    cudaGetSymbolAddress((void**)&wmhi, g_wmhi);
    cudaGetSymbolAddress((void**)&wmlo, g_wmlo);

    cudaFuncSetAttribute(bfgemm2_kernel<0>, cudaFuncAttributeMaxDynamicSharedMemorySize, GSMEM);
    cudaFuncSetAttribute(bfgemm2_kernel<1>, cudaFuncAttributeMaxDynamicSharedMemorySize, GSMEM);
    cudaFuncSetAttribute(bfgemm2_kernel<2>, cudaFuncAttributeMaxDynamicSharedMemorySize, GSMEM);
    cudaFuncSetAttribute(bfgemm2_kernel<3>, cudaFuncAttributeMaxDynamicSharedMemorySize, GSMEM);

    embed_kernel<<<(NB * NN * (ND / 4) + 255) / 256, 256>>>(x_idx, emb);
    zero_deg_kernel<<<(NN + 255) / 256, 256>>>();
    count_dst_kernel<<<(NE + 255) / 256, 256>>>(dst);
    scan_deg_kernel<<<1, 1024>>>();
    scatter_edges_kernel<<<(NE + 255) / 256, 256>>>(dst, src, ew);
    msg_agg_kernel<<<NB * NN, 128>>>(pxb, py);   // layer 0

    dim3 tpb(32, 8);
    transpose_split_kernel<<<dim3(2 * ND / 32, ND / 32, NL), tpb>>>(W1, w1hi, w1lo, ND, 2 * ND);
    transpose_split_kernel<<<dim3(ND / 32, 2 * ND / 32, NL), tpb>>>(W2, w2hi, w2lo, 2 * ND, ND);
    transpose_split_kernel<<<dim3(ND / 32, ND / 32, NLM), tpb>>>(Wm, wmhi, wmlo, ND, ND);

    const dim3 g1grid(2 * ND / 64, MP / 128);   // 16 x 157
    const dim3 g2grid(ND / 64,     MP / 128);   //  8 x 157

    for (int l = 0; l < NL; l++) {
        if (l > 0) msg_agg_kernel<<<NB * NN, 128>>>(pxb, py);
        bfgemm2_kernel<0><<<g1grid, 256, GSMEM>>>(
            2 * ND, ND, py,
            w1hi + (size_t)l * 2 * ND * ND, w1lo + (size_t)l * 2 * ND * ND,
            ph,
            b1 + (size_t)l * 2 * ND, g1 + (size_t)l * 2 * ND, be1 + (size_t)l * 2 * ND,
            nullptr, nullptr, nullptr);
        bfgemm2_kernel<1><<<g2grid, 256, GSMEM>>>(
            ND, 2 * ND, ph,
            w2hi + (size_t)l * ND * 2 * ND, w2lo + (size_t)l * ND * 2 * ND,
            pxb,
            b2 + (size_t)l * ND, nullptr, nullptr,
            nullptr, nullptr, nullptr);
    }

    ln_kernel<<<NB * NN, 128>>>(pxb, py, ln_g, ln_b);

    bfgemm2_kernel<2><<<g2grid, 256, GSMEM>>>(
        ND, ND, py, wmhi, wmlo, ph, bm, nullptr, nullptr, nullptr, nullptr, nullptr);
    bfgemm2_kernel<2><<<g2grid, 256, GSMEM>>>(
        ND, ND, ph, wmhi + (size_t)ND * ND, wmlo + (size_t)ND * ND,
        py, bm + ND, nullptr, nullptr, nullptr, nullptr, nullptr);

    zero_out_kernel<<<1, 32>>>(out);
    bfgemm2_kernel<3><<<g2grid, 256, GSMEM>>>(
        ND, ND, py, wmhi + (size_t)2 * ND * ND, wmlo + (size_t)2 * ND * ND,
        nullptr, bm + 2 * ND, nullptr, nullptr, Wout, bout, out);
}